// round 12
// baseline (speedup 1.0000x reference)
#include <cuda_runtime.h>
#include <cuda_bf16.h>
#include <cuda_fp16.h>
#include <math.h>
#include <stdint.h>

#define S_DIM 512
#define N_DIM 384
#define CIN   64
#define CZ    128
#define H_DIM 8
#define C_DIM 32
#define D_DIM 256
#define INF_  1e9f
#define EPS_  1e-5f
#define MROWS (S_DIM*N_DIM)   // 196608
#define NKC   6               // K chunks of 64 covering K=384

// ---- scratch (static device arrays: no allocations allowed) ----
__device__ float g_w [(size_t)H_DIM*N_DIM*N_DIM];   // logits [h][q][k]
__device__ __half g_g [(size_t)MROWS*D_DIM];        // gate (fp16)
__device__ __half g_o [(size_t)MROWS*D_DIM];        // attention output (fp16)
// LN(m) split-bf16, k-major rows of 64 (128B rows)
__device__ __align__(1024) __nv_bfloat16 g_mnh[(size_t)MROWS*CIN];
__device__ __align__(1024) __nv_bfloat16 g_mnl[(size_t)MROWS*CIN];
// transposed [n=512][k=64] split-bf16 weights (w_v | w_g)
__device__ __align__(1024) __nv_bfloat16 g_wth[512*64];
__device__ __align__(1024) __nv_bfloat16 g_wtl[512*64];
// transposed [n=64][k=256] split-fp16 w_o
__device__ __align__(1024) __half g_woth[64*256];
__device__ __align__(1024) __half g_wotl[64*256];
// split-bf16 k-major staging tiles, 128 rows x 64 k each (8192 elems, 16KB)
// w: [h][qt(3)][kc(6)]   v: [h][nt(128)][kc(6)]
__device__ __align__(1024) __nv_bfloat16 g_wh[(size_t)H_DIM*3*NKC*8192];
__device__ __align__(1024) __nv_bfloat16 g_wl[(size_t)H_DIM*3*NKC*8192];
__device__ __align__(1024) __nv_bfloat16 g_vh[(size_t)H_DIM*128*NKC*8192];
__device__ __align__(1024) __nv_bfloat16 g_vl[(size_t)H_DIM*128*NKC*8192];

// ============================================================
// helpers (Ampere-class ISA only: valid on base sm_103 target)
// ============================================================
__device__ __forceinline__ uint32_t smem_u32(const void* p){
    uint32_t a;
    asm("{ .reg .u64 t; cvta.to.shared.u64 t, %1; cvt.u32.u64 %0, t; }" : "=r"(a) : "l"(p));
    return a;
}
#define LDSM_X4(r0,r1,r2,r3,addr) \
    asm volatile("ldmatrix.sync.aligned.m8n8.x4.shared.b16 {%0,%1,%2,%3}, [%4];" \
        : "=r"(r0),"=r"(r1),"=r"(r2),"=r"(r3) : "r"(addr))
__device__ __forceinline__ void mma_bf16(float* c, const uint32_t* a, const uint32_t* b){
    asm volatile("mma.sync.aligned.m16n8k16.row.col.f32.bf16.bf16.f32 "
        "{%0,%1,%2,%3}, {%4,%5,%6,%7}, {%8,%9}, {%0,%1,%2,%3};"
        : "+f"(c[0]),"+f"(c[1]),"+f"(c[2]),"+f"(c[3])
        : "r"(a[0]),"r"(a[1]),"r"(a[2]),"r"(a[3]), "r"(b[0]),"r"(b[1]));
}
__device__ __forceinline__ void mma_fp16(float* c, const uint32_t* a, const uint32_t* b){
    asm volatile("mma.sync.aligned.m16n8k16.row.col.f32.f16.f16.f32 "
        "{%0,%1,%2,%3}, {%4,%5,%6,%7}, {%8,%9}, {%0,%1,%2,%3};"
        : "+f"(c[0]),"+f"(c[1]),"+f"(c[2]),"+f"(c[3])
        : "r"(a[0]),"r"(a[1]),"r"(a[2]),"r"(a[3]), "r"(b[0]),"r"(b[1]));
}
__device__ __forceinline__ void cpasync16(uint32_t dst, const void* src){
    asm volatile("cp.async.cg.shared.global [%0], [%1], 16;" :: "r"(dst), "l"(src));
}

// ============================================================
// Kernel 0a: transpose+split weights -> g_wth/g_wtl [n=512][k=64]
// ============================================================
__global__ void k_prep_w(const float* __restrict__ w_v, const float* __restrict__ w_g)
{
    int n = blockIdx.x, k = threadIdx.x;   // 512 blocks x 64 threads
    float val = (n < D_DIM) ? w_v[k*D_DIM + n] : w_g[k*D_DIM + (n - D_DIM)];
    __nv_bfloat16 hi = __float2bfloat16(val);
    __nv_bfloat16 lo = __float2bfloat16(val - __bfloat162float(hi));
    g_wth[n*64 + k] = hi;
    g_wtl[n*64 + k] = lo;
}

// ============================================================
// Kernel 0b: transpose+split w_o -> g_woth/g_wotl [n=64][k=256]
// ============================================================
__global__ void k_prep_wo(const float* __restrict__ w_o)
{
    int n = blockIdx.x, k = threadIdx.x;   // 64 blocks x 256 threads
    float val = w_o[k*CIN + n];
    __half hi = __float2half_rn(val);
    __half lo = __float2half_rn(val - __half2float(hi));
    g_woth[n*256 + k] = hi;
    g_wotl[n*256 + k] = lo;
}

// ============================================================
// Kernel 1: LN(z) + logits (warp per (q,k) row)
// ============================================================
__global__ void k_lnz_logits(const float* __restrict__ z, const float* __restrict__ mask,
                             const float* __restrict__ gamma_z, const float* __restrict__ beta_z,
                             const float* __restrict__ w_z, const float* __restrict__ b_z)
{
    int gw   = (blockIdx.x * blockDim.x + threadIdx.x) >> 5;
    int lane = threadIdx.x & 31;
    if (gw >= N_DIM * N_DIM) return;
    int q = gw / N_DIM, k = gw % N_DIM;
    const float* zp = z + (size_t)gw * CZ;

    float x0 = zp[lane], x1 = zp[lane+32], x2 = zp[lane+64], x3 = zp[lane+96];
    float s  = x0+x1+x2+x3;
    float s2 = x0*x0 + x1*x1 + x2*x2 + x3*x3;
    #pragma unroll
    for (int o = 16; o; o >>= 1) {
        s  += __shfl_xor_sync(0xffffffffu, s,  o);
        s2 += __shfl_xor_sync(0xffffffffu, s2, o);
    }
    float mu  = s * (1.0f / CZ);
    float inv = rsqrtf(s2 * (1.0f / CZ) - mu*mu + EPS_);
    float n0 = (x0-mu)*inv*gamma_z[lane]    + beta_z[lane];
    float n1 = (x1-mu)*inv*gamma_z[lane+32] + beta_z[lane+32];
    float n2 = (x2-mu)*inv*gamma_z[lane+64] + beta_z[lane+64];
    float n3 = (x3-mu)*inv*gamma_z[lane+96] + beta_z[lane+96];

    float acc[H_DIM];
    #pragma unroll
    for (int h = 0; h < H_DIM; h++) {
        acc[h] = n0 * w_z[lane*H_DIM + h]
               + n1 * w_z[(lane+32)*H_DIM + h]
               + n2 * w_z[(lane+64)*H_DIM + h]
               + n3 * w_z[(lane+96)*H_DIM + h];
        #pragma unroll
        for (int o = 16; o; o >>= 1)
            acc[h] += __shfl_xor_sync(0xffffffffu, acc[h], o);
    }
    if (lane == 0) {
        float bias = INF_ * (mask[gw] - 1.0f);
        #pragma unroll
        for (int h = 0; h < H_DIM; h++)
            g_w[((size_t)h*N_DIM + q)*N_DIM + k] = acc[h] + b_z[h] + bias;
    }
}

// ============================================================
// Kernel 2: softmax per (h,q) row -> split-bf16 staging (k-major)
// ============================================================
__global__ void k_softmax()
{
    int row = blockIdx.x;                   // h*384 + q
    int h = row / N_DIM, q = row - h*N_DIM;
    const float* p = g_w + (size_t)row * N_DIM;
    int tid = threadIdx.x;                  // 128 threads, 3 elems each
    __shared__ float red[128];

    float v0 = p[tid], v1 = p[tid+128], v2 = p[tid+256];
    float mx = fmaxf(v0, fmaxf(v1, v2));
    red[tid] = mx; __syncthreads();
    for (int o = 64; o; o >>= 1) { if (tid < o) red[tid] = fmaxf(red[tid], red[tid+o]); __syncthreads(); }
    mx = red[0]; __syncthreads();

    float e0 = expf(v0-mx), e1 = expf(v1-mx), e2 = expf(v2-mx);
    red[tid] = e0 + e1 + e2; __syncthreads();
    for (int o = 64; o; o >>= 1) { if (tid < o) red[tid] += red[tid+o]; __syncthreads(); }
    float inv = 1.0f / red[0];

    int r = q & 127;
    size_t blkbase = (size_t)((h*3 + (q >> 7)) * NKC);
    float ev[3] = {e0, e1, e2};
    #pragma unroll
    for (int t = 0; t < 3; t++) {
        int k = tid + t*128;
        float wv = ev[t] * inv;
        __nv_bfloat16 hi = __float2bfloat16(wv);
        __nv_bfloat16 lo = __float2bfloat16(wv - __bfloat162float(hi));
        int kc = k >> 6, kk = k & 63;
        size_t off = (blkbase + kc) * 8192 + (size_t)(r*64 + kk);
        g_wh[off] = hi;
        g_wl[off] = lo;
    }
}

// ============================================================
// Kernel 3: LN(m) -> split-bf16 mn (k-major rows of 64)
// ============================================================
__global__ void k_lnm(const float* __restrict__ m,
                      const float* __restrict__ gamma_m, const float* __restrict__ beta_m)
{
    int gw   = (blockIdx.x * blockDim.x + threadIdx.x) >> 5;
    int lane = threadIdx.x & 31;
    if (gw >= MROWS) return;
    const float* mp = m + (size_t)gw * CIN;
    float a = mp[lane], b = mp[lane+32];
    float s = a + b, s2 = a*a + b*b;
    #pragma unroll
    for (int o = 16; o; o >>= 1) {
        s  += __shfl_xor_sync(0xffffffffu, s,  o);
        s2 += __shfl_xor_sync(0xffffffffu, s2, o);
    }
    float mu  = s * (1.0f / CIN);
    float inv = rsqrtf(s2 * (1.0f / CIN) - mu*mu + EPS_);
    float na = (a-mu)*inv*gamma_m[lane]    + beta_m[lane];
    float nb = (b-mu)*inv*gamma_m[lane+32] + beta_m[lane+32];
    __nv_bfloat16 ha = __float2bfloat16(na);
    __nv_bfloat16 hb = __float2bfloat16(nb);
    size_t base = (size_t)gw * CIN;
    g_mnh[base + lane]      = ha;
    g_mnh[base + lane + 32] = hb;
    g_mnl[base + lane]      = __float2bfloat16(na - __bfloat162float(ha));
    g_mnl[base + lane + 32] = __float2bfloat16(nb - __bfloat162float(hb));
}

// ============================================================
// Kernel 4: v/gate projection, A-resident, 64x64 warp tiles
//   one CTA per 128 m-rows; A (32KB) + ALL B (128KB) loaded once
//   half 0: v cols 0..255 -> T-transpose (2 passes) -> staging
//   half 1: gate cols 256..511 -> sigmoid -> g_g (fp16)
// ============================================================
__global__ __launch_bounds__(256, 1) void k_gemm_vg_mma(const float* __restrict__ b_v,
                                                        const float* __restrict__ b_g)
{
    extern __shared__ __align__(128) char smem[];
    int tid = threadIdx.x;
    int m0 = blockIdx.x * 128;
    int wid = tid >> 5, lane = tid & 31;
    int warpM = wid >> 2, warpN = wid & 3;
    uint32_t sbase = smem_u32(smem);
    uint32_t sAh = sbase, sAl = sbase + 16384;
    uint32_t sBh = sbase + 32768, sBl = sbase + 98304;
    float* T = (float*)(smem + 163840);     // 128 x 129 fp32

    // ---- load A (hi+lo, 32KB) and all B (hi+lo, 128KB), swizzled ----
    {
        const char* aHi = (const char*)(g_mnh + (size_t)m0*64);
        const char* aLo = (const char*)(g_mnl + (size_t)m0*64);
        #pragma unroll
        for (int u = 0; u < 8; u++) {
            int idx = u*256 + tid;          // 0..2047
            int half = idx >> 10;
            uint32_t x = (uint32_t)(idx & 1023) * 16;
            uint32_t dst = (half ? sAl : sAh) + (x ^ ((x >> 3) & 0x70));
            cpasync16(dst, (half ? aLo : aHi) + x);
        }
        #pragma unroll
        for (int u = 0; u < 16; u++) {
            uint32_t x = (uint32_t)(u*256 + tid) * 16;   // 0..65535
            uint32_t sw = x ^ ((x >> 3) & 0x70);
            cpasync16(sBh + sw, (const char*)g_wth + x);
        }
        #pragma unroll
        for (int u = 0; u < 16; u++) {
            uint32_t x = (uint32_t)(u*256 + tid) * 16;
            uint32_t sw = x ^ ((x >> 3) & 0x70);
            cpasync16(sBl + sw, (const char*)g_wtl + x);
        }
        asm volatile("cp.async.commit_group;" ::: "memory");
        asm volatile("cp.async.wait_group 0;" ::: "memory");
        __syncthreads();
    }

    int sI = m0 / N_DIM;               // 128-row blocks never straddle s
    int kb = m0 - sI * N_DIM;          // 0,128,256
    int nt = sI >> 2;

    for (int nh = 0; nh < 2; nh++) {   // 0: v (cols 0..255), 1: gate (256..511)
        float acc[4][8][4] = {};
        #pragma unroll
        for (int kt = 0; kt < 4; kt++) {
            uint32_t a_hi[4][4], a_lo[4][4];
            #pragma unroll
            for (int mt = 0; mt < 4; mt++) {
                int row = warpM*64 + mt*16 + (lane & 15);
                uint32_t x = (uint32_t)row*128 + kt*32 + ((lane >> 4)*16);
                uint32_t sw = x ^ ((x >> 3) & 0x70);
                LDSM_X4(a_hi[mt][0], a_hi[mt][1], a_hi[mt][2], a_hi[mt][3], sAh + sw);
                LDSM_X4(a_lo[mt][0], a_lo[mt][1], a_lo[mt][2], a_lo[mt][3], sAl + sw);
            }
            #pragma unroll
            for (int bh = 0; bh < 2; bh++) {
                uint32_t b_hi[4][2], b_lo[4][2];
                #pragma unroll
                for (int p = 0; p < 2; p++) {
                    int g = lane >> 3;
                    int ntl = p*2 + (g >> 1);
                    int row = nh*256 + warpN*64 + bh*32 + ntl*8 + (lane & 7);
                    uint32_t x = (uint32_t)row*128 + kt*32 + (g & 1)*16;
                    uint32_t sw = x ^ ((x >> 3) & 0x70);
                    uint32_t r[4];
                    LDSM_X4(r[0], r[1], r[2], r[3], sBh + sw);
                    b_hi[p*2][0] = r[0]; b_hi[p*2][1] = r[1];
                    b_hi[p*2+1][0] = r[2]; b_hi[p*2+1][1] = r[3];
                    LDSM_X4(r[0], r[1], r[2], r[3], sBl + sw);
                    b_lo[p*2][0] = r[0]; b_lo[p*2][1] = r[1];
                    b_lo[p*2+1][0] = r[2]; b_lo[p*2+1][1] = r[3];
                }
                #pragma unroll
                for (int mt = 0; mt < 4; mt++)
                    #pragma unroll
                    for (int nv = 0; nv < 4; nv++)
                        mma_bf16(acc[mt][bh*4+nv], a_hi[mt], b_hi[nv]);
                #pragma unroll
                for (int mt = 0; mt < 4; mt++)
                    #pragma unroll
                    for (int nv = 0; nv < 4; nv++)
                        mma_bf16(acc[mt][bh*4+nv], a_hi[mt], b_lo[nv]);
                #pragma unroll
                for (int mt = 0; mt < 4; mt++)
                    #pragma unroll
                    for (int nv = 0; nv < 4; nv++)
                        mma_bf16(acc[mt][bh*4+nv], a_lo[mt], b_hi[nv]);
            }
        }

        if (nh == 0) {
            // ---- v epilogue: two 128-col transpose passes ----
            for (int p = 0; p < 2; p++) {
                __syncthreads();
                if ((warpN >> 1) == p) {
                    #pragma unroll
                    for (int mt = 0; mt < 4; mt++) {
                        int qr = warpM*64 + mt*16 + (lane >> 2);
                        #pragma unroll
                        for (int nn = 0; nn < 8; nn++) {
                            int ncg = warpN*64 + (nn >> 2)*32 + (nn & 3)*8 + (lane & 3)*2;
                            int ncl = ncg - p*128;       // 0..127 within pass
                            float bv0 = b_v[ncg], bv1 = b_v[ncg + 1];
                            T[(ncl  )*129 + qr    ] = acc[mt][nn][0] + bv0;
                            T[(ncl+1)*129 + qr    ] = acc[mt][nn][1] + bv1;
                            T[(ncl  )*129 + qr + 8] = acc[mt][nn][2] + bv0;
                            T[(ncl+1)*129 + qr + 8] = acc[mt][nn][3] + bv1;
                        }
                    }
                }
                __syncthreads();
                int j   = tid >> 1, kcl = tid & 1;
                int col = p*128 + j;
                int h   = col >> 5, c = col & 31;
                int nr  = ((sI & 3) << 5) + c;
                int kc  = (kb >> 6) + kcl;
                size_t blk = ((size_t)(h*128 + nt)*NKC + kc) * 8192;
                const float* Tr = T + j*129 + kcl*64;
                #pragma unroll
                for (int kk = 0; kk < 64; kk += 2) {
                    float f0 = Tr[kk], f1 = Tr[kk+1];
                    __nv_bfloat16 h0 = __float2bfloat16(f0);
                    __nv_bfloat16 h1 = __float2bfloat16(f1);
                    __nv_bfloat162 ph; ph.x = h0; ph.y = h1;
                    __nv_bfloat162 pl;
                    pl.x = __float2bfloat16(f0 - __bfloat162float(h0));
                    pl.y = __float2bfloat16(f1 - __bfloat162float(h1));
                    *(__nv_bfloat162*)&g_vh[blk + (size_t)nr*64 + kk] = ph;
                    *(__nv_bfloat162*)&g_vl[blk + (size_t)nr*64 + kk] = pl;
                }
            }
        } else {
            // ---- gate epilogue: direct fp16 stores ----
            #pragma unroll
            for (int mt = 0; mt < 4; mt++) {
                int row = m0 + warpM*64 + mt*16 + (lane >> 2);
                #pragma unroll
                for (int nn = 0; nn < 8; nn++) {
                    int jg = warpN*64 + (nn >> 2)*32 + (nn & 3)*8 + (lane & 3)*2;
                    float bg0 = b_g[jg], bg1 = b_g[jg+1];
                    float t0 = acc[mt][nn][0] + bg0, t1 = acc[mt][nn][1] + bg1;
                    float t2 = acc[mt][nn][2] + bg0, t3 = acc[mt][nn][3] + bg1;
                    *(__half2*)&g_g[(size_t)row*D_DIM + jg] =
                        __floats2half2_rn(1.0f/(1.0f+expf(-t0)), 1.0f/(1.0f+expf(-t1)));
                    *(__half2*)&g_g[(size_t)(row+8)*D_DIM + jg] =
                        __floats2half2_rn(1.0f/(1.0f+expf(-t2)), 1.0f/(1.0f+expf(-t3)));
                }
            }
        }
    }
}

// ============================================================
// Kernel 5: attention GEMM, 64x64 warp tiles (BM=128, BN=256)
//   per CTA: M=128(q) x N=256(n) x K=384; cp.async double-buffered
//   stage = Ahi|Alo (16KB ea) + Bhi|Blo (32KB ea) = 96KB, x2 stages
// ============================================================
__global__ __launch_bounds__(256, 1) void k_gemm_att_mma()
{
    extern __shared__ __align__(128) char smem[];
    const uint32_t STAGE = 98304;
    int tid = threadIdx.x;
    int qt = blockIdx.x, nt = blockIdx.y, h = blockIdx.z;
    int wid = tid >> 5, lane = tid & 31;
    int warpM = wid >> 2, warpN = wid & 3;
    uint32_t sbase = smem_u32(smem);

    const char* aHi  = (const char*)(g_wh + (size_t)(h*3   + qt) * NKC * 8192);
    const char* aLo  = (const char*)(g_wl + (size_t)(h*3   + qt) * NKC * 8192);
    const char* bHi0 = (const char*)(g_vh + (size_t)(h*128 + nt*2    ) * NKC * 8192);
    const char* bHi1 = (const char*)(g_vh + (size_t)(h*128 + nt*2 + 1) * NKC * 8192);
    const char* bLo0 = (const char*)(g_vl + (size_t)(h*128 + nt*2    ) * NKC * 8192);
    const char* bLo1 = (const char*)(g_vl + (size_t)(h*128 + nt*2 + 1) * NKC * 8192);

    float acc[4][8][4] = {};

    auto load_chunk = [&](int kc, int stage){
        size_t cb = (size_t)kc * 16384;
        #pragma unroll
        for (int t = 0; t < 24; t++) {
            int tile = t >> 2;                   // 6 tiles of 16KB
            int c    = (t & 3) * 256 + tid;
            uint32_t x = (uint32_t)c * 16;
            uint32_t dst = sbase + stage*STAGE + (uint32_t)tile*16384
                         + (x ^ ((x >> 3) & 0x70));
            const char* src =
                (tile == 0 ? aHi : tile == 1 ? aLo :
                 tile == 2 ? bHi0 : tile == 3 ? bHi1 :
                 tile == 4 ? bLo0 : bLo1) + cb + x;
            cpasync16(dst, src);
        }
        asm volatile("cp.async.commit_group;" ::: "memory");
    };

    load_chunk(0, 0);
    for (int kc = 0; kc < NKC; kc++) {
        int stage = kc & 1;
        if (kc < NKC-1) load_chunk(kc+1, stage ^ 1);
        if (kc < NKC-1) asm volatile("cp.async.wait_group 1;" ::: "memory");
        else            asm volatile("cp.async.wait_group 0;" ::: "memory");
        __syncthreads();

        uint32_t sA_hi = sbase + stage*STAGE;
        uint32_t sA_lo = sA_hi + 16384;
        uint32_t sB_hi = sA_hi + 32768;      // 32KB: rows 0..255
        uint32_t sB_lo = sA_hi + 65536;      // 32KB

        #pragma unroll
        for (int kt = 0; kt < 4; kt++) {
            uint32_t a_hi[4][4], a_lo[4][4];
            #pragma unroll
            for (int mt = 0; mt < 4; mt++) {
                int row = warpM*64 + mt*16 + (lane & 15);
                uint32_t x = (uint32_t)row*128 + kt*32 + ((lane >> 4)*16);
                uint32_t sw = x ^ ((x >> 3) & 0x70);
                LDSM_X4(a_hi[mt][0], a_hi[mt][1], a_hi[mt][2], a_hi[mt][3], sA_hi + sw);
                LDSM_X4(a_lo[mt][0], a_lo[mt][1], a_lo[mt][2], a_lo[mt][3], sA_lo + sw);
            }
            #pragma unroll
            for (int bh = 0; bh < 2; bh++) {
                uint32_t b_hi[4][2], b_lo[4][2];
                #pragma unroll
                for (int p = 0; p < 2; p++) {
                    int g = lane >> 3;
                    int ntl = p*2 + (g >> 1);
                    int row = warpN*64 + bh*32 + ntl*8 + (lane & 7);
                    uint32_t x = (uint32_t)row*128 + kt*32 + (g & 1)*16;
                    uint32_t sw = x ^ ((x >> 3) & 0x70);
                    uint32_t r[4];
                    LDSM_X4(r[0], r[1], r[2], r[3], sB_hi + sw);
                    b_hi[p*2][0] = r[0]; b_hi[p*2][1] = r[1];
                    b_hi[p*2+1][0] = r[2]; b_hi[p*2+1][1] = r[3];
                    LDSM_X4(r[0], r[1], r[2], r[3], sB_lo + sw);
                    b_lo[p*2][0] = r[0]; b_lo[p*2][1] = r[1];
                    b_lo[p*2+1][0] = r[2]; b_lo[p*2+1][1] = r[3];
                }
                #pragma unroll
                for (int mt = 0; mt < 4; mt++)
                    #pragma unroll
                    for (int nv = 0; nv < 4; nv++)
                        mma_bf16(acc[mt][bh*4+nv], a_hi[mt], b_hi[nv]);
                #pragma unroll
                for (int mt = 0; mt < 4; mt++)
                    #pragma unroll
                    for (int nv = 0; nv < 4; nv++)
                        mma_bf16(acc[mt][bh*4+nv], a_hi[mt], b_lo[nv]);
                #pragma unroll
                for (int mt = 0; mt < 4; mt++)
                    #pragma unroll
                    for (int nv = 0; nv < 4; nv++)
                        mma_bf16(acc[mt][bh*4+nv], a_lo[mt], b_hi[nv]);
            }
        }
        __syncthreads();
    }

    // ---- epilogue: fp16 stores into g_o[(s*384+q)*256 + h*32 + c] ----
    #pragma unroll
    for (int mt = 0; mt < 4; mt++) {
        int q = qt*128 + warpM*64 + mt*16 + (lane >> 2);
        #pragma unroll
        for (int nn = 0; nn < 8; nn++) {
            int n = nt*256 + warpN*64 + (nn >> 2)*32 + (nn & 3)*8 + (lane & 3)*2;
            int s = n >> 5, c = n & 31;
            size_t b0 = ((size_t)s*N_DIM + q    )*D_DIM + h*C_DIM + c;
            size_t b1 = ((size_t)s*N_DIM + q + 8)*D_DIM + h*C_DIM + c;
            *(__half2*)&g_o[b0] = __floats2half2_rn(acc[mt][nn][0], acc[mt][nn][1]);
            *(__half2*)&g_o[b1] = __floats2half2_rn(acc[mt][nn][2], acc[mt][nn][3]);
        }
    }
}

// ============================================================
// Kernel 6: output projection via mma.sync fp16 (3-term split)
// ============================================================
__global__ __launch_bounds__(256, 2) void k_gemm_out_mma(const float* __restrict__ b_o,
                                                         float* __restrict__ out)
{
    __shared__ __align__(128) char smem[49152];
    uint32_t sbase = smem_u32(smem);
    uint32_t sAh = sbase, sAl = sbase + 16384, sBh = sbase + 32768, sBl = sbase + 40960;
    int tid = threadIdx.x;
    int m0  = blockIdx.x * 128;
    int wid = tid >> 5, lane = tid & 31;
    int warpM = wid >> 1, warpN = wid & 1;

    float acc[2][4][4] = {};
    int arow = tid >> 1, ahalf = tid & 1;

    for (int k0 = 0; k0 < D_DIM; k0 += 64) {
        #pragma unroll
        for (int u = 0; u < 4; u++) {
            int idx = u*256 + tid;
            int tile = idx >> 9, rem = idx & 511;
            int n = rem >> 3, j = rem & 7;
            uint32_t x = (uint32_t)n*128 + j*16;
            uint32_t dst = (tile ? sBl : sBh) + (x ^ ((x >> 3) & 0x70));
            const __half* src = (tile ? g_wotl : g_woth) + n*256 + k0 + j*8;
            cpasync16(dst, src);
        }
        asm volatile("cp.async.commit_group;" ::: "memory");

        {
            size_t base = (size_t)(m0 + arow)*D_DIM + k0 + ahalf*32;
            uint32_t xb = (uint32_t)arow*128 + ahalf*64;
            #pragma unroll
            for (int u = 0; u < 4; u++) {
                uint4 ov = *(const uint4*)(g_o + base + u*8);
                uint4 gv = *(const uint4*)(g_g + base + u*8);
                const __half2* po = (const __half2*)&ov;
                const __half2* pg = (const __half2*)&gv;
                uint4 hv, lv;
                uint32_t* ph = (uint32_t*)&hv;
                uint32_t* pl = (uint32_t*)&lv;
                #pragma unroll
                for (int j = 0; j < 4; j++) {
                    float2 fo = __half22float2(po[j]);
                    float2 fg = __half22float2(pg[j]);
                    float p0 = fo.x * fg.x, p1 = fo.y * fg.y;
                    __half2 hh = __floats2half2_rn(p0, p1);
                    float2 hf = __half22float2(hh);
                    __half2 ll = __floats2half2_rn(p0 - hf.x, p1 - hf.y);
                    ph[j] = *(uint32_t*)&hh;
                    pl[j] = *(uint32_t*)&ll;
                }
                uint32_t x = xb + u*16;
                uint32_t sw = x ^ ((x >> 3) & 0x70);
                *(uint4*)(smem + sw)         = hv;
                *(uint4*)(smem + 16384 + sw) = lv;
            }
        }
        asm volatile("cp.async.wait_group 0;" ::: "memory");
        __syncthreads();

        #pragma unroll
        for (int kt = 0; kt < 4; kt++) {
            uint32_t a_hi[2][4], a_lo[2][4], b_hi[4][2], b_lo[4][2];
            #pragma unroll
            for (int mt = 0; mt < 2; mt++) {
                int row = warpM*32 + mt*16 + (lane & 15);
                uint32_t x = (uint32_t)row*128 + kt*32 + ((lane >> 4)*16);
                uint32_t sw = x ^ ((x >> 3) & 0x70);
                LDSM_X4(a_hi[mt][0], a_hi[mt][1], a_hi[mt][2], a_hi[mt][3], sAh + sw);
                LDSM_X4(a_lo[mt][0], a_lo[mt][1], a_lo[mt][2], a_lo[mt][3], sAl + sw);
            }
            #pragma unroll
            for (int p = 0; p < 2; p++) {
                int g = lane >> 3;
                int ntile = p*2 + (g >> 1);
                int row = warpN*32 + ntile*8 + (lane & 7);
                uint32_t x = (uint32_t)row*128 + kt*32 + (g & 1)*16;
                uint32_t sw = x ^ ((x >> 3) & 0x70);
                uint32_t r[4];
                LDSM_X4(r[0], r[1], r[2], r[3], sBh + sw);
                b_hi[p*2][0] = r[0]; b_hi[p*2][1] = r[1];
                b_hi[p*2+1][0] = r[2]; b_hi[p*2+1][1] = r[3];
                LDSM_X4(r[0], r[1], r[2], r[3], sBl + sw);
                b_lo[p*2][0] = r[0]; b_lo[p*2][1] = r[1];
                b_lo[p*2+1][0] = r[2]; b_lo[p*2+1][1] = r[3];
            }
            #pragma unroll
            for (int mt = 0; mt < 2; mt++)
                #pragma unroll
                for (int nn = 0; nn < 4; nn++)
                    mma_fp16(acc[mt][nn], a_hi[mt], b_hi[nn]);
            #pragma unroll
            for (int mt = 0; mt < 2; mt++)
                #pragma unroll
                for (int nn = 0; nn < 4; nn++)
                    mma_fp16(acc[mt][nn], a_lo[mt], b_hi[nn]);
            #pragma unroll
            for (int mt = 0; mt < 2; mt++)
                #pragma unroll
                for (int nn = 0; nn < 4; nn++)
                    mma_fp16(acc[mt][nn], a_hi[mt], b_lo[nn]);
        }
        __syncthreads();
    }

    #pragma unroll
    for (int mt = 0; mt < 2; mt++) {
        int row = m0 + warpM*32 + mt*16 + (lane >> 2);
        #pragma unroll
        for (int nn = 0; nn < 4; nn++) {
            int col = warpN*32 + nn*8 + (lane & 3)*2;
            float b0 = b_o[col], b1 = b_o[col+1];
            *(float2*)(out + (size_t)row*CIN + col) =
                make_float2(acc[mt][nn][0] + b0, acc[mt][nn][1] + b1);
            *(float2*)(out + (size_t)(row+8)*CIN + col) =
                make_float2(acc[mt][nn][2] + b0, acc[mt][nn][3] + b1);
        }
    }
}

// ============================================================
extern "C" void kernel_launch(void* const* d_in, const int* in_sizes, int n_in,
                              void* d_out, int out_size)
{
    const float* m       = (const float*)d_in[0];
    const float* z       = (const float*)d_in[1];
    const float* mask    = (const float*)d_in[2];
    const float* gamma_m = (const float*)d_in[3];
    const float* beta_m  = (const float*)d_in[4];
    const float* gamma_z = (const float*)d_in[5];
    const float* beta_z  = (const float*)d_in[6];
    const float* w_z     = (const float*)d_in[7];
    const float* b_z     = (const float*)d_in[8];
    const float* w_v     = (const float*)d_in[9];
    const float* b_v     = (const float*)d_in[10];
    const float* w_g     = (const float*)d_in[11];
    const float* b_g     = (const float*)d_in[12];
    const float* w_o     = (const float*)d_in[13];
    const float* b_o     = (const float*)d_in[14];
    float* out = (float*)d_out;

    cudaFuncSetAttribute(k_gemm_att_mma, cudaFuncAttributeMaxDynamicSharedMemorySize, 196608);
    cudaFuncSetAttribute(k_gemm_vg_mma,  cudaFuncAttributeMaxDynamicSharedMemorySize, 229888);

    k_prep_w<<<512, 64>>>(w_v, w_g);
    k_prep_wo<<<64, 256>>>(w_o);
    k_lnz_logits<<<(N_DIM*N_DIM)/8, 256>>>(z, mask, gamma_z, beta_z, w_z, b_z);
    k_softmax<<<H_DIM*N_DIM, 128>>>();
    k_lnm<<<MROWS/8, 256>>>(m, gamma_m, beta_m);
    k_gemm_vg_mma<<<MROWS/128, 256, 229888>>>(b_v, b_g);
    k_gemm_att_mma<<<dim3(3, 64, 8), 256, 196608>>>();
    k_gemm_out_mma<<<MROWS/128, 256>>>(b_o, out);
}

// round 13
// speedup vs baseline: 1.1032x; 1.1032x over previous
#include <cuda_runtime.h>
#include <cuda_bf16.h>
#include <cuda_fp16.h>
#include <math.h>
#include <stdint.h>

#define S_DIM 512
#define N_DIM 384
#define CIN   64
#define CZ    128
#define H_DIM 8
#define C_DIM 32
#define D_DIM 256
#define INF_  1e9f
#define EPS_  1e-5f
#define MROWS (S_DIM*N_DIM)   // 196608
#define NKC   6               // K chunks of 64 covering K=384

// ---- scratch (static device arrays: no allocations allowed) ----
__device__ float g_w [(size_t)H_DIM*N_DIM*N_DIM];   // logits [h][q][k]
__device__ __half g_g [(size_t)MROWS*D_DIM];        // gate (fp16)
__device__ __half g_o [(size_t)MROWS*D_DIM];        // attention output (fp16)
// LN(m) split-bf16, k-major rows of 64 (128B rows)
__device__ __align__(1024) __nv_bfloat16 g_mnh[(size_t)MROWS*CIN];
__device__ __align__(1024) __nv_bfloat16 g_mnl[(size_t)MROWS*CIN];
// transposed [n=512][k=64] split-bf16 weights (w_v | w_g)
__device__ __align__(1024) __nv_bfloat16 g_wth[512*64];
__device__ __align__(1024) __nv_bfloat16 g_wtl[512*64];
// transposed [n=64][k=256] split-fp16 w_o
__device__ __align__(1024) __half g_woth[64*256];
__device__ __align__(1024) __half g_wotl[64*256];
// split-bf16 k-major staging tiles, 128 rows x 64 k each (8192 elems, 16KB)
// w: [h][qt(3)][kc(6)]   v: [h][nt(128)][kc(6)]
__device__ __align__(1024) __nv_bfloat16 g_wh[(size_t)H_DIM*3*NKC*8192];
__device__ __align__(1024) __nv_bfloat16 g_wl[(size_t)H_DIM*3*NKC*8192];
__device__ __align__(1024) __nv_bfloat16 g_vh[(size_t)H_DIM*128*NKC*8192];
__device__ __align__(1024) __nv_bfloat16 g_vl[(size_t)H_DIM*128*NKC*8192];

// ============================================================
// helpers (Ampere-class ISA only: valid on base sm_103 target)
// ============================================================
__device__ __forceinline__ uint32_t smem_u32(const void* p){
    uint32_t a;
    asm("{ .reg .u64 t; cvta.to.shared.u64 t, %1; cvt.u32.u64 %0, t; }" : "=r"(a) : "l"(p));
    return a;
}
#define LDSM_X4(r0,r1,r2,r3,addr) \
    asm volatile("ldmatrix.sync.aligned.m8n8.x4.shared.b16 {%0,%1,%2,%3}, [%4];" \
        : "=r"(r0),"=r"(r1),"=r"(r2),"=r"(r3) : "r"(addr))
__device__ __forceinline__ void mma_bf16(float* c, const uint32_t* a, const uint32_t* b){
    asm volatile("mma.sync.aligned.m16n8k16.row.col.f32.bf16.bf16.f32 "
        "{%0,%1,%2,%3}, {%4,%5,%6,%7}, {%8,%9}, {%0,%1,%2,%3};"
        : "+f"(c[0]),"+f"(c[1]),"+f"(c[2]),"+f"(c[3])
        : "r"(a[0]),"r"(a[1]),"r"(a[2]),"r"(a[3]), "r"(b[0]),"r"(b[1]));
}
__device__ __forceinline__ void mma_fp16(float* c, const uint32_t* a, const uint32_t* b){
    asm volatile("mma.sync.aligned.m16n8k16.row.col.f32.f16.f16.f32 "
        "{%0,%1,%2,%3}, {%4,%5,%6,%7}, {%8,%9}, {%0,%1,%2,%3};"
        : "+f"(c[0]),"+f"(c[1]),"+f"(c[2]),"+f"(c[3])
        : "r"(a[0]),"r"(a[1]),"r"(a[2]),"r"(a[3]), "r"(b[0]),"r"(b[1]));
}
__device__ __forceinline__ void cpasync16(uint32_t dst, const void* src){
    asm volatile("cp.async.cg.shared.global [%0], [%1], 16;" :: "r"(dst), "l"(src));
}

// ============================================================
// Kernel 0a: transpose+split weights -> g_wth/g_wtl [n=512][k=64]
// ============================================================
__global__ void k_prep_w(const float* __restrict__ w_v, const float* __restrict__ w_g)
{
    int n = blockIdx.x, k = threadIdx.x;   // 512 blocks x 64 threads
    float val = (n < D_DIM) ? w_v[k*D_DIM + n] : w_g[k*D_DIM + (n - D_DIM)];
    __nv_bfloat16 hi = __float2bfloat16(val);
    __nv_bfloat16 lo = __float2bfloat16(val - __bfloat162float(hi));
    g_wth[n*64 + k] = hi;
    g_wtl[n*64 + k] = lo;
}

// ============================================================
// Kernel 0b: transpose+split w_o -> g_woth/g_wotl [n=64][k=256]
// ============================================================
__global__ void k_prep_wo(const float* __restrict__ w_o)
{
    int n = blockIdx.x, k = threadIdx.x;   // 64 blocks x 256 threads
    float val = w_o[k*CIN + n];
    __half hi = __float2half_rn(val);
    __half lo = __float2half_rn(val - __half2float(hi));
    g_woth[n*256 + k] = hi;
    g_wotl[n*256 + k] = lo;
}

// ============================================================
// Kernel 1: LN(z) + logits (warp per (q,k) row)
// ============================================================
__global__ void k_lnz_logits(const float* __restrict__ z, const float* __restrict__ mask,
                             const float* __restrict__ gamma_z, const float* __restrict__ beta_z,
                             const float* __restrict__ w_z, const float* __restrict__ b_z)
{
    int gw   = (blockIdx.x * blockDim.x + threadIdx.x) >> 5;
    int lane = threadIdx.x & 31;
    if (gw >= N_DIM * N_DIM) return;
    int q = gw / N_DIM, k = gw % N_DIM;
    const float* zp = z + (size_t)gw * CZ;

    float x0 = zp[lane], x1 = zp[lane+32], x2 = zp[lane+64], x3 = zp[lane+96];
    float s  = x0+x1+x2+x3;
    float s2 = x0*x0 + x1*x1 + x2*x2 + x3*x3;
    #pragma unroll
    for (int o = 16; o; o >>= 1) {
        s  += __shfl_xor_sync(0xffffffffu, s,  o);
        s2 += __shfl_xor_sync(0xffffffffu, s2, o);
    }
    float mu  = s * (1.0f / CZ);
    float inv = rsqrtf(s2 * (1.0f / CZ) - mu*mu + EPS_);
    float n0 = (x0-mu)*inv*gamma_z[lane]    + beta_z[lane];
    float n1 = (x1-mu)*inv*gamma_z[lane+32] + beta_z[lane+32];
    float n2 = (x2-mu)*inv*gamma_z[lane+64] + beta_z[lane+64];
    float n3 = (x3-mu)*inv*gamma_z[lane+96] + beta_z[lane+96];

    float acc[H_DIM];
    #pragma unroll
    for (int h = 0; h < H_DIM; h++) {
        acc[h] = n0 * w_z[lane*H_DIM + h]
               + n1 * w_z[(lane+32)*H_DIM + h]
               + n2 * w_z[(lane+64)*H_DIM + h]
               + n3 * w_z[(lane+96)*H_DIM + h];
        #pragma unroll
        for (int o = 16; o; o >>= 1)
            acc[h] += __shfl_xor_sync(0xffffffffu, acc[h], o);
    }
    if (lane == 0) {
        float bias = INF_ * (mask[gw] - 1.0f);
        #pragma unroll
        for (int h = 0; h < H_DIM; h++)
            g_w[((size_t)h*N_DIM + q)*N_DIM + k] = acc[h] + b_z[h] + bias;
    }
}

// ============================================================
// Kernel 2: softmax per (h,q) row -> split-bf16 staging (k-major)
// ============================================================
__global__ void k_softmax()
{
    int row = blockIdx.x;                   // h*384 + q
    int h = row / N_DIM, q = row - h*N_DIM;
    const float* p = g_w + (size_t)row * N_DIM;
    int tid = threadIdx.x;                  // 128 threads, 3 elems each
    __shared__ float red[128];

    float v0 = p[tid], v1 = p[tid+128], v2 = p[tid+256];
    float mx = fmaxf(v0, fmaxf(v1, v2));
    red[tid] = mx; __syncthreads();
    for (int o = 64; o; o >>= 1) { if (tid < o) red[tid] = fmaxf(red[tid], red[tid+o]); __syncthreads(); }
    mx = red[0]; __syncthreads();

    float e0 = expf(v0-mx), e1 = expf(v1-mx), e2 = expf(v2-mx);
    red[tid] = e0 + e1 + e2; __syncthreads();
    for (int o = 64; o; o >>= 1) { if (tid < o) red[tid] += red[tid+o]; __syncthreads(); }
    float inv = 1.0f / red[0];

    int r = q & 127;
    size_t blkbase = (size_t)((h*3 + (q >> 7)) * NKC);
    float ev[3] = {e0, e1, e2};
    #pragma unroll
    for (int t = 0; t < 3; t++) {
        int k = tid + t*128;
        float wv = ev[t] * inv;
        __nv_bfloat16 hi = __float2bfloat16(wv);
        __nv_bfloat16 lo = __float2bfloat16(wv - __bfloat162float(hi));
        int kc = k >> 6, kk = k & 63;
        size_t off = (blkbase + kc) * 8192 + (size_t)(r*64 + kk);
        g_wh[off] = hi;
        g_wl[off] = lo;
    }
}

// ============================================================
// Kernel 3: LN(m) -> split-bf16 mn (k-major rows of 64)
// ============================================================
__global__ void k_lnm(const float* __restrict__ m,
                      const float* __restrict__ gamma_m, const float* __restrict__ beta_m)
{
    int gw   = (blockIdx.x * blockDim.x + threadIdx.x) >> 5;
    int lane = threadIdx.x & 31;
    if (gw >= MROWS) return;
    const float* mp = m + (size_t)gw * CIN;
    float a = mp[lane], b = mp[lane+32];
    float s = a + b, s2 = a*a + b*b;
    #pragma unroll
    for (int o = 16; o; o >>= 1) {
        s  += __shfl_xor_sync(0xffffffffu, s,  o);
        s2 += __shfl_xor_sync(0xffffffffu, s2, o);
    }
    float mu  = s * (1.0f / CIN);
    float inv = rsqrtf(s2 * (1.0f / CIN) - mu*mu + EPS_);
    float na = (a-mu)*inv*gamma_m[lane]    + beta_m[lane];
    float nb = (b-mu)*inv*gamma_m[lane+32] + beta_m[lane+32];
    __nv_bfloat16 ha = __float2bfloat16(na);
    __nv_bfloat16 hb = __float2bfloat16(nb);
    size_t base = (size_t)gw * CIN;
    g_mnh[base + lane]      = ha;
    g_mnh[base + lane + 32] = hb;
    g_mnl[base + lane]      = __float2bfloat16(na - __bfloat162float(ha));
    g_mnl[base + lane + 32] = __float2bfloat16(nb - __bfloat162float(hb));
}

// ============================================================
// Kernel 4: v/gate projection via mma.sync bf16 (3-term split)
//   R11-proven version: grid (4, 1536), 66KB smem, 3 CTAs/SM;
//   adjacent n-tiles reuse the A block via L2.
// ============================================================
__global__ __launch_bounds__(256, 1) void k_gemm_vg_mma(const float* __restrict__ b_v,
                                                        const float* __restrict__ b_g)
{
    extern __shared__ __align__(128) char smem[];
    int tid = threadIdx.x;
    int n0 = blockIdx.x * 128;
    int m0 = blockIdx.y * 128;
    int wid = tid >> 5, lane = tid & 31;
    int warpM = wid >> 2, warpN = wid & 3;
    uint32_t sbase = smem_u32(smem);

    const char* aHi = (const char*)(g_mnh + (size_t)m0*64);
    const char* aLo = (const char*)(g_mnl + (size_t)m0*64);
    const char* bHi = (const char*)(g_wth + (size_t)n0*64);
    const char* bLo = (const char*)(g_wtl + (size_t)n0*64);

    #pragma unroll
    for (int t = 0; t < 16; t++) {
        int tile = t >> 2;
        int c    = (t & 3) * 256 + tid;
        uint32_t x = (uint32_t)c * 16;
        uint32_t dst = sbase + (uint32_t)tile*16384 + (x ^ ((x >> 3) & 0x70));
        const char* src = (tile == 0 ? aHi : tile == 1 ? aLo : tile == 2 ? bHi : bLo) + x;
        cpasync16(dst, src);
    }
    asm volatile("cp.async.commit_group;" ::: "memory");
    asm volatile("cp.async.wait_group 0;" ::: "memory");
    __syncthreads();

    uint32_t sA_hi = sbase;
    uint32_t sA_lo = sbase + 16384;
    uint32_t sB_hi = sbase + 32768;
    uint32_t sB_lo = sbase + 49152;

    float acc[4][4][4] = {};
    #pragma unroll
    for (int kt = 0; kt < 4; kt++) {
        uint32_t a_hi[4][4], a_lo[4][4], b_hi[4][2], b_lo[4][2];
        #pragma unroll
        for (int mt = 0; mt < 4; mt++) {
            int row = warpM*64 + mt*16 + (lane & 15);
            uint32_t x = (uint32_t)row*128 + kt*32 + ((lane >> 4)*16);
            uint32_t sw = x ^ ((x >> 3) & 0x70);
            LDSM_X4(a_hi[mt][0], a_hi[mt][1], a_hi[mt][2], a_hi[mt][3], sA_hi + sw);
            LDSM_X4(a_lo[mt][0], a_lo[mt][1], a_lo[mt][2], a_lo[mt][3], sA_lo + sw);
        }
        #pragma unroll
        for (int p = 0; p < 2; p++) {
            int g = lane >> 3;
            int ntile = p*2 + (g >> 1);
            int row = warpN*32 + ntile*8 + (lane & 7);
            uint32_t x = (uint32_t)row*128 + kt*32 + (g & 1)*16;
            uint32_t sw = x ^ ((x >> 3) & 0x70);
            uint32_t r[4];
            LDSM_X4(r[0], r[1], r[2], r[3], sB_hi + sw);
            b_hi[p*2][0] = r[0]; b_hi[p*2][1] = r[1];
            b_hi[p*2+1][0] = r[2]; b_hi[p*2+1][1] = r[3];
            LDSM_X4(r[0], r[1], r[2], r[3], sB_lo + sw);
            b_lo[p*2][0] = r[0]; b_lo[p*2][1] = r[1];
            b_lo[p*2+1][0] = r[2]; b_lo[p*2+1][1] = r[3];
        }
        #pragma unroll
        for (int mt = 0; mt < 4; mt++)
            #pragma unroll
            for (int nn = 0; nn < 4; nn++)
                mma_bf16(acc[mt][nn], a_hi[mt], b_hi[nn]);
        #pragma unroll
        for (int mt = 0; mt < 4; mt++)
            #pragma unroll
            for (int nn = 0; nn < 4; nn++)
                mma_bf16(acc[mt][nn], a_hi[mt], b_lo[nn]);
        #pragma unroll
        for (int mt = 0; mt < 4; mt++)
            #pragma unroll
            for (int nn = 0; nn < 4; nn++)
                mma_bf16(acc[mt][nn], a_lo[mt], b_hi[nn]);
    }
    __syncthreads();

    if (n0 < D_DIM) {
        float* T = (float*)smem;   // 128 x 129
        #pragma unroll
        for (int mt = 0; mt < 4; mt++) {
            int qr = warpM*64 + mt*16 + (lane >> 2);
            #pragma unroll
            for (int nn = 0; nn < 4; nn++) {
                int nc = warpN*32 + nn*8 + (lane & 3)*2;
                float bv0 = b_v[n0 + nc], bv1 = b_v[n0 + nc + 1];
                T[(nc  )*129 + qr    ] = acc[mt][nn][0] + bv0;
                T[(nc+1)*129 + qr    ] = acc[mt][nn][1] + bv1;
                T[(nc  )*129 + qr + 8] = acc[mt][nn][2] + bv0;
                T[(nc+1)*129 + qr + 8] = acc[mt][nn][3] + bv1;
            }
        }
        __syncthreads();

        int sI = m0 / N_DIM;
        int kb = m0 - sI * N_DIM;
        int nt = sI >> 2;
        int j   = tid >> 1, kcl = tid & 1;
        int col = n0 + j;
        int h   = col >> 5, c = col & 31;
        int nr  = ((sI & 3) << 5) + c;
        int kc  = (kb >> 6) + kcl;
        size_t blk = ((size_t)(h*128 + nt)*NKC + kc) * 8192;
        const float* Tr = T + j*129 + kcl*64;
        #pragma unroll
        for (int kk = 0; kk < 64; kk += 2) {
            float f0 = Tr[kk], f1 = Tr[kk+1];
            __nv_bfloat16 h0 = __float2bfloat16(f0);
            __nv_bfloat16 h1 = __float2bfloat16(f1);
            __nv_bfloat162 ph; ph.x = h0; ph.y = h1;
            __nv_bfloat162 pl;
            pl.x = __float2bfloat16(f0 - __bfloat162float(h0));
            pl.y = __float2bfloat16(f1 - __bfloat162float(h1));
            *(__nv_bfloat162*)&g_vh[blk + (size_t)nr*64 + kk] = ph;
            *(__nv_bfloat162*)&g_vl[blk + (size_t)nr*64 + kk] = pl;
        }
    } else {
        int jb = n0 - D_DIM;
        #pragma unroll
        for (int mt = 0; mt < 4; mt++) {
            int row = m0 + warpM*64 + mt*16 + (lane >> 2);
            #pragma unroll
            for (int nn = 0; nn < 4; nn++) {
                int jg = jb + warpN*32 + nn*8 + (lane & 3)*2;
                float bg0 = b_g[jg], bg1 = b_g[jg+1];
                float t0 = acc[mt][nn][0] + bg0, t1 = acc[mt][nn][1] + bg1;
                float t2 = acc[mt][nn][2] + bg0, t3 = acc[mt][nn][3] + bg1;
                *(__half2*)&g_g[(size_t)row*D_DIM + jg] =
                    __floats2half2_rn(1.0f/(1.0f+expf(-t0)), 1.0f/(1.0f+expf(-t1)));
                *(__half2*)&g_g[(size_t)(row+8)*D_DIM + jg] =
                    __floats2half2_rn(1.0f/(1.0f+expf(-t2)), 1.0f/(1.0f+expf(-t3)));
            }
        }
    }
}

// ============================================================
// Kernel 5: attention GEMM, 64x64 warp tiles (BM=128, BN=256)
//   per CTA: M=128(q) x N=256(n) x K=384; cp.async double-buffered
//   stage = Ahi|Alo (16KB ea) + Bhi|Blo (32KB ea) = 96KB, x2 stages
// ============================================================
__global__ __launch_bounds__(256, 1) void k_gemm_att_mma()
{
    extern __shared__ __align__(128) char smem[];
    const uint32_t STAGE = 98304;
    int tid = threadIdx.x;
    int qt = blockIdx.x, nt = blockIdx.y, h = blockIdx.z;
    int wid = tid >> 5, lane = tid & 31;
    int warpM = wid >> 2, warpN = wid & 3;
    uint32_t sbase = smem_u32(smem);

    const char* aHi  = (const char*)(g_wh + (size_t)(h*3   + qt) * NKC * 8192);
    const char* aLo  = (const char*)(g_wl + (size_t)(h*3   + qt) * NKC * 8192);
    const char* bHi0 = (const char*)(g_vh + (size_t)(h*128 + nt*2    ) * NKC * 8192);
    const char* bHi1 = (const char*)(g_vh + (size_t)(h*128 + nt*2 + 1) * NKC * 8192);
    const char* bLo0 = (const char*)(g_vl + (size_t)(h*128 + nt*2    ) * NKC * 8192);
    const char* bLo1 = (const char*)(g_vl + (size_t)(h*128 + nt*2 + 1) * NKC * 8192);

    float acc[4][8][4] = {};

    auto load_chunk = [&](int kc, int stage){
        size_t cb = (size_t)kc * 16384;
        #pragma unroll
        for (int t = 0; t < 24; t++) {
            int tile = t >> 2;                   // 6 tiles of 16KB
            int c    = (t & 3) * 256 + tid;
            uint32_t x = (uint32_t)c * 16;
            uint32_t dst = sbase + stage*STAGE + (uint32_t)tile*16384
                         + (x ^ ((x >> 3) & 0x70));
            const char* src =
                (tile == 0 ? aHi : tile == 1 ? aLo :
                 tile == 2 ? bHi0 : tile == 3 ? bHi1 :
                 tile == 4 ? bLo0 : bLo1) + cb + x;
            cpasync16(dst, src);
        }
        asm volatile("cp.async.commit_group;" ::: "memory");
    };

    load_chunk(0, 0);
    for (int kc = 0; kc < NKC; kc++) {
        int stage = kc & 1;
        if (kc < NKC-1) load_chunk(kc+1, stage ^ 1);
        if (kc < NKC-1) asm volatile("cp.async.wait_group 1;" ::: "memory");
        else            asm volatile("cp.async.wait_group 0;" ::: "memory");
        __syncthreads();

        uint32_t sA_hi = sbase + stage*STAGE;
        uint32_t sA_lo = sA_hi + 16384;
        uint32_t sB_hi = sA_hi + 32768;      // 32KB: rows 0..255
        uint32_t sB_lo = sA_hi + 65536;      // 32KB

        #pragma unroll
        for (int kt = 0; kt < 4; kt++) {
            uint32_t a_hi[4][4], a_lo[4][4];
            #pragma unroll
            for (int mt = 0; mt < 4; mt++) {
                int row = warpM*64 + mt*16 + (lane & 15);
                uint32_t x = (uint32_t)row*128 + kt*32 + ((lane >> 4)*16);
                uint32_t sw = x ^ ((x >> 3) & 0x70);
                LDSM_X4(a_hi[mt][0], a_hi[mt][1], a_hi[mt][2], a_hi[mt][3], sA_hi + sw);
                LDSM_X4(a_lo[mt][0], a_lo[mt][1], a_lo[mt][2], a_lo[mt][3], sA_lo + sw);
            }
            #pragma unroll
            for (int bh = 0; bh < 2; bh++) {
                uint32_t b_hi[4][2], b_lo[4][2];
                #pragma unroll
                for (int p = 0; p < 2; p++) {
                    int g = lane >> 3;
                    int ntl = p*2 + (g >> 1);
                    int row = warpN*64 + bh*32 + ntl*8 + (lane & 7);
                    uint32_t x = (uint32_t)row*128 + kt*32 + (g & 1)*16;
                    uint32_t sw = x ^ ((x >> 3) & 0x70);
                    uint32_t r[4];
                    LDSM_X4(r[0], r[1], r[2], r[3], sB_hi + sw);
                    b_hi[p*2][0] = r[0]; b_hi[p*2][1] = r[1];
                    b_hi[p*2+1][0] = r[2]; b_hi[p*2+1][1] = r[3];
                    LDSM_X4(r[0], r[1], r[2], r[3], sB_lo + sw);
                    b_lo[p*2][0] = r[0]; b_lo[p*2][1] = r[1];
                    b_lo[p*2+1][0] = r[2]; b_lo[p*2+1][1] = r[3];
                }
                #pragma unroll
                for (int mt = 0; mt < 4; mt++)
                    #pragma unroll
                    for (int nv = 0; nv < 4; nv++)
                        mma_bf16(acc[mt][bh*4+nv], a_hi[mt], b_hi[nv]);
                #pragma unroll
                for (int mt = 0; mt < 4; mt++)
                    #pragma unroll
                    for (int nv = 0; nv < 4; nv++)
                        mma_bf16(acc[mt][bh*4+nv], a_hi[mt], b_lo[nv]);
                #pragma unroll
                for (int mt = 0; mt < 4; mt++)
                    #pragma unroll
                    for (int nv = 0; nv < 4; nv++)
                        mma_bf16(acc[mt][bh*4+nv], a_lo[mt], b_hi[nv]);
            }
        }
        __syncthreads();
    }

    // ---- epilogue: fp16 stores into g_o[(s*384+q)*256 + h*32 + c] ----
    #pragma unroll
    for (int mt = 0; mt < 4; mt++) {
        int q = qt*128 + warpM*64 + mt*16 + (lane >> 2);
        #pragma unroll
        for (int nn = 0; nn < 8; nn++) {
            int n = nt*256 + warpN*64 + (nn >> 2)*32 + (nn & 3)*8 + (lane & 3)*2;
            int s = n >> 5, c = n & 31;
            size_t b0 = ((size_t)s*N_DIM + q    )*D_DIM + h*C_DIM + c;
            size_t b1 = ((size_t)s*N_DIM + q + 8)*D_DIM + h*C_DIM + c;
            *(__half2*)&g_o[b0] = __floats2half2_rn(acc[mt][nn][0], acc[mt][nn][1]);
            *(__half2*)&g_o[b1] = __floats2half2_rn(acc[mt][nn][2], acc[mt][nn][3]);
        }
    }
}

// ============================================================
// Kernel 6: output projection via mma.sync fp16 (3-term split)
// ============================================================
__global__ __launch_bounds__(256, 2) void k_gemm_out_mma(const float* __restrict__ b_o,
                                                         float* __restrict__ out)
{
    __shared__ __align__(128) char smem[49152];
    uint32_t sbase = smem_u32(smem);
    uint32_t sAh = sbase, sAl = sbase + 16384, sBh = sbase + 32768, sBl = sbase + 40960;
    int tid = threadIdx.x;
    int m0  = blockIdx.x * 128;
    int wid = tid >> 5, lane = tid & 31;
    int warpM = wid >> 1, warpN = wid & 1;

    float acc[2][4][4] = {};
    int arow = tid >> 1, ahalf = tid & 1;

    for (int k0 = 0; k0 < D_DIM; k0 += 64) {
        #pragma unroll
        for (int u = 0; u < 4; u++) {
            int idx = u*256 + tid;
            int tile = idx >> 9, rem = idx & 511;
            int n = rem >> 3, j = rem & 7;
            uint32_t x = (uint32_t)n*128 + j*16;
            uint32_t dst = (tile ? sBl : sBh) + (x ^ ((x >> 3) & 0x70));
            const __half* src = (tile ? g_wotl : g_woth) + n*256 + k0 + j*8;
            cpasync16(dst, src);
        }
        asm volatile("cp.async.commit_group;" ::: "memory");

        {
            size_t base = (size_t)(m0 + arow)*D_DIM + k0 + ahalf*32;
            uint32_t xb = (uint32_t)arow*128 + ahalf*64;
            #pragma unroll
            for (int u = 0; u < 4; u++) {
                uint4 ov = *(const uint4*)(g_o + base + u*8);
                uint4 gv = *(const uint4*)(g_g + base + u*8);
                const __half2* po = (const __half2*)&ov;
                const __half2* pg = (const __half2*)&gv;
                uint4 hv, lv;
                uint32_t* ph = (uint32_t*)&hv;
                uint32_t* pl = (uint32_t*)&lv;
                #pragma unroll
                for (int j = 0; j < 4; j++) {
                    float2 fo = __half22float2(po[j]);
                    float2 fg = __half22float2(pg[j]);
                    float p0 = fo.x * fg.x, p1 = fo.y * fg.y;
                    __half2 hh = __floats2half2_rn(p0, p1);
                    float2 hf = __half22float2(hh);
                    __half2 ll = __floats2half2_rn(p0 - hf.x, p1 - hf.y);
                    ph[j] = *(uint32_t*)&hh;
                    pl[j] = *(uint32_t*)&ll;
                }
                uint32_t x = xb + u*16;
                uint32_t sw = x ^ ((x >> 3) & 0x70);
                *(uint4*)(smem + sw)         = hv;
                *(uint4*)(smem + 16384 + sw) = lv;
            }
        }
        asm volatile("cp.async.wait_group 0;" ::: "memory");
        __syncthreads();

        #pragma unroll
        for (int kt = 0; kt < 4; kt++) {
            uint32_t a_hi[2][4], a_lo[2][4], b_hi[4][2], b_lo[4][2];
            #pragma unroll
            for (int mt = 0; mt < 2; mt++) {
                int row = warpM*32 + mt*16 + (lane & 15);
                uint32_t x = (uint32_t)row*128 + kt*32 + ((lane >> 4)*16);
                uint32_t sw = x ^ ((x >> 3) & 0x70);
                LDSM_X4(a_hi[mt][0], a_hi[mt][1], a_hi[mt][2], a_hi[mt][3], sAh + sw);
                LDSM_X4(a_lo[mt][0], a_lo[mt][1], a_lo[mt][2], a_lo[mt][3], sAl + sw);
            }
            #pragma unroll
            for (int p = 0; p < 2; p++) {
                int g = lane >> 3;
                int ntile = p*2 + (g >> 1);
                int row = warpN*32 + ntile*8 + (lane & 7);
                uint32_t x = (uint32_t)row*128 + kt*32 + (g & 1)*16;
                uint32_t sw = x ^ ((x >> 3) & 0x70);
                uint32_t r[4];
                LDSM_X4(r[0], r[1], r[2], r[3], sBh + sw);
                b_hi[p*2][0] = r[0]; b_hi[p*2][1] = r[1];
                b_hi[p*2+1][0] = r[2]; b_hi[p*2+1][1] = r[3];
                LDSM_X4(r[0], r[1], r[2], r[3], sBl + sw);
                b_lo[p*2][0] = r[0]; b_lo[p*2][1] = r[1];
                b_lo[p*2+1][0] = r[2]; b_lo[p*2+1][1] = r[3];
            }
            #pragma unroll
            for (int mt = 0; mt < 2; mt++)
                #pragma unroll
                for (int nn = 0; nn < 4; nn++)
                    mma_fp16(acc[mt][nn], a_hi[mt], b_hi[nn]);
            #pragma unroll
            for (int mt = 0; mt < 2; mt++)
                #pragma unroll
                for (int nn = 0; nn < 4; nn++)
                    mma_fp16(acc[mt][nn], a_lo[mt], b_hi[nn]);
            #pragma unroll
            for (int mt = 0; mt < 2; mt++)
                #pragma unroll
                for (int nn = 0; nn < 4; nn++)
                    mma_fp16(acc[mt][nn], a_hi[mt], b_lo[nn]);
        }
        __syncthreads();
    }

    #pragma unroll
    for (int mt = 0; mt < 2; mt++) {
        int row = m0 + warpM*32 + mt*16 + (lane >> 2);
        #pragma unroll
        for (int nn = 0; nn < 4; nn++) {
            int col = warpN*32 + nn*8 + (lane & 3)*2;
            float b0 = b_o[col], b1 = b_o[col+1];
            *(float2*)(out + (size_t)row*CIN + col) =
                make_float2(acc[mt][nn][0] + b0, acc[mt][nn][1] + b1);
            *(float2*)(out + (size_t)(row+8)*CIN + col) =
                make_float2(acc[mt][nn][2] + b0, acc[mt][nn][3] + b1);
        }
    }
}

// ============================================================
extern "C" void kernel_launch(void* const* d_in, const int* in_sizes, int n_in,
                              void* d_out, int out_size)
{
    const float* m       = (const float*)d_in[0];
    const float* z       = (const float*)d_in[1];
    const float* mask    = (const float*)d_in[2];
    const float* gamma_m = (const float*)d_in[3];
    const float* beta_m  = (const float*)d_in[4];
    const float* gamma_z = (const float*)d_in[5];
    const float* beta_z  = (const float*)d_in[6];
    const float* w_z     = (const float*)d_in[7];
    const float* b_z     = (const float*)d_in[8];
    const float* w_v     = (const float*)d_in[9];
    const float* b_v     = (const float*)d_in[10];
    const float* w_g     = (const float*)d_in[11];
    const float* b_g     = (const float*)d_in[12];
    const float* w_o     = (const float*)d_in[13];
    const float* b_o     = (const float*)d_in[14];
    float* out = (float*)d_out;

    cudaFuncSetAttribute(k_gemm_att_mma, cudaFuncAttributeMaxDynamicSharedMemorySize, 196608);
    cudaFuncSetAttribute(k_gemm_vg_mma,  cudaFuncAttributeMaxDynamicSharedMemorySize, 66048);

    k_prep_w<<<512, 64>>>(w_v, w_g);
    k_prep_wo<<<64, 256>>>(w_o);
    k_lnz_logits<<<(N_DIM*N_DIM)/8, 256>>>(z, mask, gamma_z, beta_z, w_z, b_z);
    k_softmax<<<H_DIM*N_DIM, 128>>>();
    k_lnm<<<MROWS/8, 256>>>(m, gamma_m, beta_m);
    k_gemm_vg_mma<<<dim3(4, MROWS/128), 256, 66048>>>(b_v, b_g);
    k_gemm_att_mma<<<dim3(3, 64, 8), 256, 196608>>>();
    k_gemm_out_mma<<<MROWS/128, 256>>>(b_o, out);
}

// round 14
// speedup vs baseline: 1.4142x; 1.2819x over previous
#include <cuda_runtime.h>
#include <cuda_bf16.h>
#include <cuda_fp16.h>
#include <math.h>
#include <stdint.h>

#define S_DIM 512
#define N_DIM 384
#define CIN   64
#define CZ    128
#define H_DIM 8
#define C_DIM 32
#define D_DIM 256
#define INF_  1e9f
#define EPS_  1e-5f
#define MROWS (S_DIM*N_DIM)   // 196608
#define NKC   6               // K chunks of 64 covering K=384

// ---- scratch (static device arrays: no allocations allowed) ----
__device__ float g_w [(size_t)H_DIM*N_DIM*N_DIM];   // logits [h][q][k]
__device__ __half g_g [(size_t)MROWS*D_DIM];        // gate (fp16)
__device__ __half g_o [(size_t)MROWS*D_DIM];        // attention output (fp16)
// LN(m) split-bf16, k-major rows of 64 (128B rows)
__device__ __align__(1024) __nv_bfloat16 g_mnh[(size_t)MROWS*CIN];
__device__ __align__(1024) __nv_bfloat16 g_mnl[(size_t)MROWS*CIN];
// transposed [n=512][k=64] split-bf16 weights (w_v | w_g)
__device__ __align__(1024) __nv_bfloat16 g_wth[512*64];
__device__ __align__(1024) __nv_bfloat16 g_wtl[512*64];
// transposed [n=64][k=256] split-fp16 w_o
__device__ __align__(1024) __half g_woth[64*256];
__device__ __align__(1024) __half g_wotl[64*256];
// SINGLE-fp16 k-major staging tiles, 128 rows x 64 k each (8192 elems, 16KB)
// w: [h][qt(3)][kc(6)]   v: [h][nt(128)][kc(6)]
__device__ __align__(1024) __half g_wh[(size_t)H_DIM*3*NKC*8192];
__device__ __align__(1024) __half g_vh[(size_t)H_DIM*128*NKC*8192];

// ============================================================
// helpers (Ampere-class ISA only: valid on base sm_103 target)
// ============================================================
__device__ __forceinline__ uint32_t smem_u32(const void* p){
    uint32_t a;
    asm("{ .reg .u64 t; cvta.to.shared.u64 t, %1; cvt.u32.u64 %0, t; }" : "=r"(a) : "l"(p));
    return a;
}
#define LDSM_X4(r0,r1,r2,r3,addr) \
    asm volatile("ldmatrix.sync.aligned.m8n8.x4.shared.b16 {%0,%1,%2,%3}, [%4];" \
        : "=r"(r0),"=r"(r1),"=r"(r2),"=r"(r3) : "r"(addr))
__device__ __forceinline__ void mma_bf16(float* c, const uint32_t* a, const uint32_t* b){
    asm volatile("mma.sync.aligned.m16n8k16.row.col.f32.bf16.bf16.f32 "
        "{%0,%1,%2,%3}, {%4,%5,%6,%7}, {%8,%9}, {%0,%1,%2,%3};"
        : "+f"(c[0]),"+f"(c[1]),"+f"(c[2]),"+f"(c[3])
        : "r"(a[0]),"r"(a[1]),"r"(a[2]),"r"(a[3]), "r"(b[0]),"r"(b[1]));
}
__device__ __forceinline__ void mma_fp16(float* c, const uint32_t* a, const uint32_t* b){
    asm volatile("mma.sync.aligned.m16n8k16.row.col.f32.f16.f16.f32 "
        "{%0,%1,%2,%3}, {%4,%5,%6,%7}, {%8,%9}, {%0,%1,%2,%3};"
        : "+f"(c[0]),"+f"(c[1]),"+f"(c[2]),"+f"(c[3])
        : "r"(a[0]),"r"(a[1]),"r"(a[2]),"r"(a[3]), "r"(b[0]),"r"(b[1]));
}
__device__ __forceinline__ void cpasync16(uint32_t dst, const void* src){
    asm volatile("cp.async.cg.shared.global [%0], [%1], 16;" :: "r"(dst), "l"(src));
}

// ============================================================
// Kernel 0a: transpose+split weights -> g_wth/g_wtl [n=512][k=64]
// ============================================================
__global__ void k_prep_w(const float* __restrict__ w_v, const float* __restrict__ w_g)
{
    int n = blockIdx.x, k = threadIdx.x;   // 512 blocks x 64 threads
    float val = (n < D_DIM) ? w_v[k*D_DIM + n] : w_g[k*D_DIM + (n - D_DIM)];
    __nv_bfloat16 hi = __float2bfloat16(val);
    __nv_bfloat16 lo = __float2bfloat16(val - __bfloat162float(hi));
    g_wth[n*64 + k] = hi;
    g_wtl[n*64 + k] = lo;
}

// ============================================================
// Kernel 0b: transpose+split w_o -> g_woth/g_wotl [n=64][k=256]
// ============================================================
__global__ void k_prep_wo(const float* __restrict__ w_o)
{
    int n = blockIdx.x, k = threadIdx.x;   // 64 blocks x 256 threads
    float val = w_o[k*CIN + n];
    __half hi = __float2half_rn(val);
    __half lo = __float2half_rn(val - __half2float(hi));
    g_woth[n*256 + k] = hi;
    g_wotl[n*256 + k] = lo;
}

// ============================================================
// Kernel 1: LN(z) + logits (warp per (q,k) row)
// ============================================================
__global__ void k_lnz_logits(const float* __restrict__ z, const float* __restrict__ mask,
                             const float* __restrict__ gamma_z, const float* __restrict__ beta_z,
                             const float* __restrict__ w_z, const float* __restrict__ b_z)
{
    int gw   = (blockIdx.x * blockDim.x + threadIdx.x) >> 5;
    int lane = threadIdx.x & 31;
    if (gw >= N_DIM * N_DIM) return;
    int q = gw / N_DIM, k = gw % N_DIM;
    const float* zp = z + (size_t)gw * CZ;

    float x0 = zp[lane], x1 = zp[lane+32], x2 = zp[lane+64], x3 = zp[lane+96];
    float s  = x0+x1+x2+x3;
    float s2 = x0*x0 + x1*x1 + x2*x2 + x3*x3;
    #pragma unroll
    for (int o = 16; o; o >>= 1) {
        s  += __shfl_xor_sync(0xffffffffu, s,  o);
        s2 += __shfl_xor_sync(0xffffffffu, s2, o);
    }
    float mu  = s * (1.0f / CZ);
    float inv = rsqrtf(s2 * (1.0f / CZ) - mu*mu + EPS_);
    float n0 = (x0-mu)*inv*gamma_z[lane]    + beta_z[lane];
    float n1 = (x1-mu)*inv*gamma_z[lane+32] + beta_z[lane+32];
    float n2 = (x2-mu)*inv*gamma_z[lane+64] + beta_z[lane+64];
    float n3 = (x3-mu)*inv*gamma_z[lane+96] + beta_z[lane+96];

    float acc[H_DIM];
    #pragma unroll
    for (int h = 0; h < H_DIM; h++) {
        acc[h] = n0 * w_z[lane*H_DIM + h]
               + n1 * w_z[(lane+32)*H_DIM + h]
               + n2 * w_z[(lane+64)*H_DIM + h]
               + n3 * w_z[(lane+96)*H_DIM + h];
        #pragma unroll
        for (int o = 16; o; o >>= 1)
            acc[h] += __shfl_xor_sync(0xffffffffu, acc[h], o);
    }
    if (lane == 0) {
        float bias = INF_ * (mask[gw] - 1.0f);
        #pragma unroll
        for (int h = 0; h < H_DIM; h++)
            g_w[((size_t)h*N_DIM + q)*N_DIM + k] = acc[h] + b_z[h] + bias;
    }
}

// ============================================================
// Kernel 2: softmax per (h,q) row -> single-fp16 staging (k-major)
// ============================================================
__global__ void k_softmax()
{
    int row = blockIdx.x;                   // h*384 + q
    int h = row / N_DIM, q = row - h*N_DIM;
    const float* p = g_w + (size_t)row * N_DIM;
    int tid = threadIdx.x;                  // 128 threads, 3 elems each
    __shared__ float red[128];

    float v0 = p[tid], v1 = p[tid+128], v2 = p[tid+256];
    float mx = fmaxf(v0, fmaxf(v1, v2));
    red[tid] = mx; __syncthreads();
    for (int o = 64; o; o >>= 1) { if (tid < o) red[tid] = fmaxf(red[tid], red[tid+o]); __syncthreads(); }
    mx = red[0]; __syncthreads();

    float e0 = expf(v0-mx), e1 = expf(v1-mx), e2 = expf(v2-mx);
    red[tid] = e0 + e1 + e2; __syncthreads();
    for (int o = 64; o; o >>= 1) { if (tid < o) red[tid] += red[tid+o]; __syncthreads(); }
    float inv = 1.0f / red[0];

    int r = q & 127;
    size_t blkbase = (size_t)((h*3 + (q >> 7)) * NKC);
    float ev[3] = {e0, e1, e2};
    #pragma unroll
    for (int t = 0; t < 3; t++) {
        int k = tid + t*128;
        float wv = ev[t] * inv;
        int kc = k >> 6, kk = k & 63;
        size_t off = (blkbase + kc) * 8192 + (size_t)(r*64 + kk);
        g_wh[off] = __float2half_rn(wv);
    }
}

// ============================================================
// Kernel 3: LN(m) -> split-bf16 mn (k-major rows of 64)
// ============================================================
__global__ void k_lnm(const float* __restrict__ m,
                      const float* __restrict__ gamma_m, const float* __restrict__ beta_m)
{
    int gw   = (blockIdx.x * blockDim.x + threadIdx.x) >> 5;
    int lane = threadIdx.x & 31;
    if (gw >= MROWS) return;
    const float* mp = m + (size_t)gw * CIN;
    float a = mp[lane], b = mp[lane+32];
    float s = a + b, s2 = a*a + b*b;
    #pragma unroll
    for (int o = 16; o; o >>= 1) {
        s  += __shfl_xor_sync(0xffffffffu, s,  o);
        s2 += __shfl_xor_sync(0xffffffffu, s2, o);
    }
    float mu  = s * (1.0f / CIN);
    float inv = rsqrtf(s2 * (1.0f / CIN) - mu*mu + EPS_);
    float na = (a-mu)*inv*gamma_m[lane]    + beta_m[lane];
    float nb = (b-mu)*inv*gamma_m[lane+32] + beta_m[lane+32];
    __nv_bfloat16 ha = __float2bfloat16(na);
    __nv_bfloat16 hb = __float2bfloat16(nb);
    size_t base = (size_t)gw * CIN;
    g_mnh[base + lane]      = ha;
    g_mnh[base + lane + 32] = hb;
    g_mnl[base + lane]      = __float2bfloat16(na - __bfloat162float(ha));
    g_mnl[base + lane + 32] = __float2bfloat16(nb - __bfloat162float(hb));
}

// ============================================================
// Kernel 4: v/gate projection via mma.sync bf16 (3-term split)
//   R11-proven grid (4, 1536), 66KB smem; v epilogue now emits
//   single-fp16 staging (half the store traffic)
// ============================================================
__global__ __launch_bounds__(256, 1) void k_gemm_vg_mma(const float* __restrict__ b_v,
                                                        const float* __restrict__ b_g)
{
    extern __shared__ __align__(128) char smem[];
    int tid = threadIdx.x;
    int n0 = blockIdx.x * 128;
    int m0 = blockIdx.y * 128;
    int wid = tid >> 5, lane = tid & 31;
    int warpM = wid >> 2, warpN = wid & 3;
    uint32_t sbase = smem_u32(smem);

    const char* aHi = (const char*)(g_mnh + (size_t)m0*64);
    const char* aLo = (const char*)(g_mnl + (size_t)m0*64);
    const char* bHi = (const char*)(g_wth + (size_t)n0*64);
    const char* bLo = (const char*)(g_wtl + (size_t)n0*64);

    #pragma unroll
    for (int t = 0; t < 16; t++) {
        int tile = t >> 2;
        int c    = (t & 3) * 256 + tid;
        uint32_t x = (uint32_t)c * 16;
        uint32_t dst = sbase + (uint32_t)tile*16384 + (x ^ ((x >> 3) & 0x70));
        const char* src = (tile == 0 ? aHi : tile == 1 ? aLo : tile == 2 ? bHi : bLo) + x;
        cpasync16(dst, src);
    }
    asm volatile("cp.async.commit_group;" ::: "memory");
    asm volatile("cp.async.wait_group 0;" ::: "memory");
    __syncthreads();

    uint32_t sA_hi = sbase;
    uint32_t sA_lo = sbase + 16384;
    uint32_t sB_hi = sbase + 32768;
    uint32_t sB_lo = sbase + 49152;

    float acc[4][4][4] = {};
    #pragma unroll
    for (int kt = 0; kt < 4; kt++) {
        uint32_t a_hi[4][4], a_lo[4][4], b_hi[4][2], b_lo[4][2];
        #pragma unroll
        for (int mt = 0; mt < 4; mt++) {
            int row = warpM*64 + mt*16 + (lane & 15);
            uint32_t x = (uint32_t)row*128 + kt*32 + ((lane >> 4)*16);
            uint32_t sw = x ^ ((x >> 3) & 0x70);
            LDSM_X4(a_hi[mt][0], a_hi[mt][1], a_hi[mt][2], a_hi[mt][3], sA_hi + sw);
            LDSM_X4(a_lo[mt][0], a_lo[mt][1], a_lo[mt][2], a_lo[mt][3], sA_lo + sw);
        }
        #pragma unroll
        for (int p = 0; p < 2; p++) {
            int g = lane >> 3;
            int ntile = p*2 + (g >> 1);
            int row = warpN*32 + ntile*8 + (lane & 7);
            uint32_t x = (uint32_t)row*128 + kt*32 + (g & 1)*16;
            uint32_t sw = x ^ ((x >> 3) & 0x70);
            uint32_t r[4];
            LDSM_X4(r[0], r[1], r[2], r[3], sB_hi + sw);
            b_hi[p*2][0] = r[0]; b_hi[p*2][1] = r[1];
            b_hi[p*2+1][0] = r[2]; b_hi[p*2+1][1] = r[3];
            LDSM_X4(r[0], r[1], r[2], r[3], sB_lo + sw);
            b_lo[p*2][0] = r[0]; b_lo[p*2][1] = r[1];
            b_lo[p*2+1][0] = r[2]; b_lo[p*2+1][1] = r[3];
        }
        #pragma unroll
        for (int mt = 0; mt < 4; mt++)
            #pragma unroll
            for (int nn = 0; nn < 4; nn++)
                mma_bf16(acc[mt][nn], a_hi[mt], b_hi[nn]);
        #pragma unroll
        for (int mt = 0; mt < 4; mt++)
            #pragma unroll
            for (int nn = 0; nn < 4; nn++)
                mma_bf16(acc[mt][nn], a_hi[mt], b_lo[nn]);
        #pragma unroll
        for (int mt = 0; mt < 4; mt++)
            #pragma unroll
            for (int nn = 0; nn < 4; nn++)
                mma_bf16(acc[mt][nn], a_lo[mt], b_hi[nn]);
    }
    __syncthreads();

    if (n0 < D_DIM) {
        float* T = (float*)smem;   // 128 x 129
        #pragma unroll
        for (int mt = 0; mt < 4; mt++) {
            int qr = warpM*64 + mt*16 + (lane >> 2);
            #pragma unroll
            for (int nn = 0; nn < 4; nn++) {
                int nc = warpN*32 + nn*8 + (lane & 3)*2;
                float bv0 = b_v[n0 + nc], bv1 = b_v[n0 + nc + 1];
                T[(nc  )*129 + qr    ] = acc[mt][nn][0] + bv0;
                T[(nc+1)*129 + qr    ] = acc[mt][nn][1] + bv1;
                T[(nc  )*129 + qr + 8] = acc[mt][nn][2] + bv0;
                T[(nc+1)*129 + qr + 8] = acc[mt][nn][3] + bv1;
            }
        }
        __syncthreads();

        int sI = m0 / N_DIM;
        int kb = m0 - sI * N_DIM;
        int nt = sI >> 2;
        int j   = tid >> 1, kcl = tid & 1;
        int col = n0 + j;
        int h   = col >> 5, c = col & 31;
        int nr  = ((sI & 3) << 5) + c;
        int kc  = (kb >> 6) + kcl;
        size_t blk = ((size_t)(h*128 + nt)*NKC + kc) * 8192;
        const float* Tr = T + j*129 + kcl*64;
        #pragma unroll
        for (int kk = 0; kk < 64; kk += 2) {
            *(__half2*)&g_vh[blk + (size_t)nr*64 + kk] =
                __floats2half2_rn(Tr[kk], Tr[kk+1]);
        }
    } else {
        int jb = n0 - D_DIM;
        #pragma unroll
        for (int mt = 0; mt < 4; mt++) {
            int row = m0 + warpM*64 + mt*16 + (lane >> 2);
            #pragma unroll
            for (int nn = 0; nn < 4; nn++) {
                int jg = jb + warpN*32 + nn*8 + (lane & 3)*2;
                float bg0 = b_g[jg], bg1 = b_g[jg+1];
                float t0 = acc[mt][nn][0] + bg0, t1 = acc[mt][nn][1] + bg1;
                float t2 = acc[mt][nn][2] + bg0, t3 = acc[mt][nn][3] + bg1;
                *(__half2*)&g_g[(size_t)row*D_DIM + jg] =
                    __floats2half2_rn(1.0f/(1.0f+expf(-t0)), 1.0f/(1.0f+expf(-t1)));
                *(__half2*)&g_g[(size_t)(row+8)*D_DIM + jg] =
                    __floats2half2_rn(1.0f/(1.0f+expf(-t2)), 1.0f/(1.0f+expf(-t3)));
            }
        }
    }
}

// ============================================================
// Kernel 5: attention GEMM, SINGLE fp16 operands, 64x64 warp
//   tiles (BM=128, BN=256); 1 MMA per tile (was 3);
//   stage = A 16KB + B 32KB = 48KB, x2 stages
// ============================================================
__global__ __launch_bounds__(256, 1) void k_gemm_att_mma()
{
    extern __shared__ __align__(128) char smem[];
    const uint32_t STAGE = 49152;
    int tid = threadIdx.x;
    int qt = blockIdx.x, nt = blockIdx.y, h = blockIdx.z;
    int wid = tid >> 5, lane = tid & 31;
    int warpM = wid >> 2, warpN = wid & 3;
    uint32_t sbase = smem_u32(smem);

    const char* aH  = (const char*)(g_wh + (size_t)(h*3   + qt) * NKC * 8192);
    const char* bH0 = (const char*)(g_vh + (size_t)(h*128 + nt*2    ) * NKC * 8192);
    const char* bH1 = (const char*)(g_vh + (size_t)(h*128 + nt*2 + 1) * NKC * 8192);

    float acc[4][8][4] = {};

    auto load_chunk = [&](int kc, int stage){
        size_t cb = (size_t)kc * 16384;
        #pragma unroll
        for (int t = 0; t < 12; t++) {
            int tile = t >> 2;                   // 3 tiles of 16KB
            int c    = (t & 3) * 256 + tid;
            uint32_t x = (uint32_t)c * 16;
            uint32_t dst = sbase + stage*STAGE + (uint32_t)tile*16384
                         + (x ^ ((x >> 3) & 0x70));
            const char* src = (tile == 0 ? aH : tile == 1 ? bH0 : bH1) + cb + x;
            cpasync16(dst, src);
        }
        asm volatile("cp.async.commit_group;" ::: "memory");
    };

    load_chunk(0, 0);
    for (int kc = 0; kc < NKC; kc++) {
        int stage = kc & 1;
        if (kc < NKC-1) load_chunk(kc+1, stage ^ 1);
        if (kc < NKC-1) asm volatile("cp.async.wait_group 1;" ::: "memory");
        else            asm volatile("cp.async.wait_group 0;" ::: "memory");
        __syncthreads();

        uint32_t sA = sbase + stage*STAGE;
        uint32_t sB = sA + 16384;            // 32KB: rows 0..255

        #pragma unroll
        for (int kt = 0; kt < 4; kt++) {
            uint32_t a[4][4], b[8][2];
            #pragma unroll
            for (int mt = 0; mt < 4; mt++) {
                int row = warpM*64 + mt*16 + (lane & 15);
                uint32_t x = (uint32_t)row*128 + kt*32 + ((lane >> 4)*16);
                uint32_t sw = x ^ ((x >> 3) & 0x70);
                LDSM_X4(a[mt][0], a[mt][1], a[mt][2], a[mt][3], sA + sw);
            }
            #pragma unroll
            for (int bh = 0; bh < 2; bh++) {
                #pragma unroll
                for (int p = 0; p < 2; p++) {
                    int g = lane >> 3;
                    int ntl = p*2 + (g >> 1);
                    int row = warpN*64 + bh*32 + ntl*8 + (lane & 7);
                    uint32_t x = (uint32_t)row*128 + kt*32 + (g & 1)*16;
                    uint32_t sw = x ^ ((x >> 3) & 0x70);
                    uint32_t r[4];
                    LDSM_X4(r[0], r[1], r[2], r[3], sB + sw);
                    b[bh*4 + p*2    ][0] = r[0]; b[bh*4 + p*2    ][1] = r[1];
                    b[bh*4 + p*2 + 1][0] = r[2]; b[bh*4 + p*2 + 1][1] = r[3];
                }
            }
            #pragma unroll
            for (int mt = 0; mt < 4; mt++)
                #pragma unroll
                for (int nn = 0; nn < 8; nn++)
                    mma_fp16(acc[mt][nn], a[mt], b[nn]);
        }
        __syncthreads();
    }

    // ---- epilogue: fp16 stores into g_o[(s*384+q)*256 + h*32 + c] ----
    #pragma unroll
    for (int mt = 0; mt < 4; mt++) {
        int q = qt*128 + warpM*64 + mt*16 + (lane >> 2);
        #pragma unroll
        for (int nn = 0; nn < 8; nn++) {
            int n = nt*256 + warpN*64 + (nn >> 2)*32 + (nn & 3)*8 + (lane & 3)*2;
            int s = n >> 5, c = n & 31;
            size_t b0 = ((size_t)s*N_DIM + q    )*D_DIM + h*C_DIM + c;
            size_t b1 = ((size_t)s*N_DIM + q + 8)*D_DIM + h*C_DIM + c;
            *(__half2*)&g_o[b0] = __floats2half2_rn(acc[mt][nn][0], acc[mt][nn][1]);
            *(__half2*)&g_o[b1] = __floats2half2_rn(acc[mt][nn][2], acc[mt][nn][3]);
        }
    }
}

// ============================================================
// Kernel 6: output projection via mma.sync fp16 (3-term split)
// ============================================================
__global__ __launch_bounds__(256, 2) void k_gemm_out_mma(const float* __restrict__ b_o,
                                                         float* __restrict__ out)
{
    __shared__ __align__(128) char smem[49152];
    uint32_t sbase = smem_u32(smem);
    uint32_t sAh = sbase, sAl = sbase + 16384, sBh = sbase + 32768, sBl = sbase + 40960;
    int tid = threadIdx.x;
    int m0  = blockIdx.x * 128;
    int wid = tid >> 5, lane = tid & 31;
    int warpM = wid >> 1, warpN = wid & 1;

    float acc[2][4][4] = {};
    int arow = tid >> 1, ahalf = tid & 1;

    for (int k0 = 0; k0 < D_DIM; k0 += 64) {
        #pragma unroll
        for (int u = 0; u < 4; u++) {
            int idx = u*256 + tid;
            int tile = idx >> 9, rem = idx & 511;
            int n = rem >> 3, j = rem & 7;
            uint32_t x = (uint32_t)n*128 + j*16;
            uint32_t dst = (tile ? sBl : sBh) + (x ^ ((x >> 3) & 0x70));
            const __half* src = (tile ? g_wotl : g_woth) + n*256 + k0 + j*8;
            cpasync16(dst, src);
        }
        asm volatile("cp.async.commit_group;" ::: "memory");

        {
            size_t base = (size_t)(m0 + arow)*D_DIM + k0 + ahalf*32;
            uint32_t xb = (uint32_t)arow*128 + ahalf*64;
            #pragma unroll
            for (int u = 0; u < 4; u++) {
                uint4 ov = *(const uint4*)(g_o + base + u*8);
                uint4 gv = *(const uint4*)(g_g + base + u*8);
                const __half2* po = (const __half2*)&ov;
                const __half2* pg = (const __half2*)&gv;
                uint4 hv, lv;
                uint32_t* ph = (uint32_t*)&hv;
                uint32_t* pl = (uint32_t*)&lv;
                #pragma unroll
                for (int j = 0; j < 4; j++) {
                    float2 fo = __half22float2(po[j]);
                    float2 fg = __half22float2(pg[j]);
                    float p0 = fo.x * fg.x, p1 = fo.y * fg.y;
                    __half2 hh = __floats2half2_rn(p0, p1);
                    float2 hf = __half22float2(hh);
                    __half2 ll = __floats2half2_rn(p0 - hf.x, p1 - hf.y);
                    ph[j] = *(uint32_t*)&hh;
                    pl[j] = *(uint32_t*)&ll;
                }
                uint32_t x = xb + u*16;
                uint32_t sw = x ^ ((x >> 3) & 0x70);
                *(uint4*)(smem + sw)         = hv;
                *(uint4*)(smem + 16384 + sw) = lv;
            }
        }
        asm volatile("cp.async.wait_group 0;" ::: "memory");
        __syncthreads();

        #pragma unroll
        for (int kt = 0; kt < 4; kt++) {
            uint32_t a_hi[2][4], a_lo[2][4], b_hi[4][2], b_lo[4][2];
            #pragma unroll
            for (int mt = 0; mt < 2; mt++) {
                int row = warpM*32 + mt*16 + (lane & 15);
                uint32_t x = (uint32_t)row*128 + kt*32 + ((lane >> 4)*16);
                uint32_t sw = x ^ ((x >> 3) & 0x70);
                LDSM_X4(a_hi[mt][0], a_hi[mt][1], a_hi[mt][2], a_hi[mt][3], sAh + sw);
                LDSM_X4(a_lo[mt][0], a_lo[mt][1], a_lo[mt][2], a_lo[mt][3], sAl + sw);
            }
            #pragma unroll
            for (int p = 0; p < 2; p++) {
                int g = lane >> 3;
                int ntile = p*2 + (g >> 1);
                int row = warpN*32 + ntile*8 + (lane & 7);
                uint32_t x = (uint32_t)row*128 + kt*32 + (g & 1)*16;
                uint32_t sw = x ^ ((x >> 3) & 0x70);
                uint32_t r[4];
                LDSM_X4(r[0], r[1], r[2], r[3], sBh + sw);
                b_hi[p*2][0] = r[0]; b_hi[p*2][1] = r[1];
                b_hi[p*2+1][0] = r[2]; b_hi[p*2+1][1] = r[3];
                LDSM_X4(r[0], r[1], r[2], r[3], sBl + sw);
                b_lo[p*2][0] = r[0]; b_lo[p*2][1] = r[1];
                b_lo[p*2+1][0] = r[2]; b_lo[p*2+1][1] = r[3];
            }
            #pragma unroll
            for (int mt = 0; mt < 2; mt++)
                #pragma unroll
                for (int nn = 0; nn < 4; nn++)
                    mma_fp16(acc[mt][nn], a_hi[mt], b_hi[nn]);
            #pragma unroll
            for (int mt = 0; mt < 2; mt++)
                #pragma unroll
                for (int nn = 0; nn < 4; nn++)
                    mma_fp16(acc[mt][nn], a_lo[mt], b_hi[nn]);
            #pragma unroll
            for (int mt = 0; mt < 2; mt++)
                #pragma unroll
                for (int nn = 0; nn < 4; nn++)
                    mma_fp16(acc[mt][nn], a_hi[mt], b_lo[nn]);
        }
        __syncthreads();
    }

    #pragma unroll
    for (int mt = 0; mt < 2; mt++) {
        int row = m0 + warpM*32 + mt*16 + (lane >> 2);
        #pragma unroll
        for (int nn = 0; nn < 4; nn++) {
            int col = warpN*32 + nn*8 + (lane & 3)*2;
            float b0 = b_o[col], b1 = b_o[col+1];
            *(float2*)(out + (size_t)row*CIN + col) =
                make_float2(acc[mt][nn][0] + b0, acc[mt][nn][1] + b1);
            *(float2*)(out + (size_t)(row+8)*CIN + col) =
                make_float2(acc[mt][nn][2] + b0, acc[mt][nn][3] + b1);
        }
    }
}

// ============================================================
extern "C" void kernel_launch(void* const* d_in, const int* in_sizes, int n_in,
                              void* d_out, int out_size)
{
    const float* m       = (const float*)d_in[0];
    const float* z       = (const float*)d_in[1];
    const float* mask    = (const float*)d_in[2];
    const float* gamma_m = (const float*)d_in[3];
    const float* beta_m  = (const float*)d_in[4];
    const float* gamma_z = (const float*)d_in[5];
    const float* beta_z  = (const float*)d_in[6];
    const float* w_z     = (const float*)d_in[7];
    const float* b_z     = (const float*)d_in[8];
    const float* w_v     = (const float*)d_in[9];
    const float* b_v     = (const float*)d_in[10];
    const float* w_g     = (const float*)d_in[11];
    const float* b_g     = (const float*)d_in[12];
    const float* w_o     = (const float*)d_in[13];
    const float* b_o     = (const float*)d_in[14];
    float* out = (float*)d_out;

    cudaFuncSetAttribute(k_gemm_att_mma, cudaFuncAttributeMaxDynamicSharedMemorySize, 98304);
    cudaFuncSetAttribute(k_gemm_vg_mma,  cudaFuncAttributeMaxDynamicSharedMemorySize, 66048);

    k_prep_w<<<512, 64>>>(w_v, w_g);
    k_prep_wo<<<64, 256>>>(w_o);
    k_lnz_logits<<<(N_DIM*N_DIM)/8, 256>>>(z, mask, gamma_z, beta_z, w_z, b_z);
    k_softmax<<<H_DIM*N_DIM, 128>>>();
    k_lnm<<<MROWS/8, 256>>>(m, gamma_m, beta_m);
    k_gemm_vg_mma<<<dim3(4, MROWS/128), 256, 66048>>>(b_v, b_g);
    k_gemm_att_mma<<<dim3(3, 64, 8), 256, 98304>>>();
    k_gemm_out_mma<<<MROWS/128, 256>>>(b_o, out);
}

// round 15
// speedup vs baseline: 1.5509x; 1.0967x over previous
#include <cuda_runtime.h>
#include <cuda_bf16.h>
#include <cuda_fp16.h>
#include <math.h>
#include <stdint.h>

#define S_DIM 512
#define N_DIM 384
#define CIN   64
#define CZ    128
#define H_DIM 8
#define C_DIM 32
#define D_DIM 256
#define INF_  1e9f
#define EPS_  1e-5f
#define MROWS (S_DIM*N_DIM)   // 196608
#define NKC   6               // K chunks of 64 covering K=384

// ---- scratch (static device arrays: no allocations allowed) ----
__device__ float g_w [(size_t)H_DIM*N_DIM*N_DIM];   // logits [h][q][k]
__device__ __half g_g [(size_t)MROWS*D_DIM];        // gate (fp16)
__device__ __half g_o [(size_t)MROWS*D_DIM];        // attention output (fp16)
// LN(m) single-fp16, k-major rows of 64 (128B rows)
__device__ __align__(1024) __half g_mn16[(size_t)MROWS*CIN];
// transposed [n=512][k=64] single-fp16 weights (w_v | w_g)
__device__ __align__(1024) __half g_wt16[512*64];
// transposed [n=64][k=256] split-fp16 w_o
__device__ __align__(1024) __half g_woth[64*256];
__device__ __align__(1024) __half g_wotl[64*256];
// SINGLE-fp16 k-major staging tiles, 128 rows x 64 k each (8192 elems, 16KB)
// w: [h][qt(3)][kc(6)]   v: [h][nt(128)][kc(6)]
__device__ __align__(1024) __half g_wh[(size_t)H_DIM*3*NKC*8192];
__device__ __align__(1024) __half g_vh[(size_t)H_DIM*128*NKC*8192];

// ============================================================
// helpers (Ampere-class ISA only: valid on base sm_103 target)
// ============================================================
__device__ __forceinline__ uint32_t smem_u32(const void* p){
    uint32_t a;
    asm("{ .reg .u64 t; cvta.to.shared.u64 t, %1; cvt.u32.u64 %0, t; }" : "=r"(a) : "l"(p));
    return a;
}
#define LDSM_X4(r0,r1,r2,r3,addr) \
    asm volatile("ldmatrix.sync.aligned.m8n8.x4.shared.b16 {%0,%1,%2,%3}, [%4];" \
        : "=r"(r0),"=r"(r1),"=r"(r2),"=r"(r3) : "r"(addr))
__device__ __forceinline__ void mma_fp16(float* c, const uint32_t* a, const uint32_t* b){
    asm volatile("mma.sync.aligned.m16n8k16.row.col.f32.f16.f16.f32 "
        "{%0,%1,%2,%3}, {%4,%5,%6,%7}, {%8,%9}, {%0,%1,%2,%3};"
        : "+f"(c[0]),"+f"(c[1]),"+f"(c[2]),"+f"(c[3])
        : "r"(a[0]),"r"(a[1]),"r"(a[2]),"r"(a[3]), "r"(b[0]),"r"(b[1]));
}
__device__ __forceinline__ void cpasync16(uint32_t dst, const void* src){
    asm volatile("cp.async.cg.shared.global [%0], [%1], 16;" :: "r"(dst), "l"(src));
}

// ============================================================
// Kernel 0a: transpose weights -> g_wt16 [n=512][k=64] (fp16)
// ============================================================
__global__ void k_prep_w(const float* __restrict__ w_v, const float* __restrict__ w_g)
{
    int n = blockIdx.x, k = threadIdx.x;   // 512 blocks x 64 threads
    float val = (n < D_DIM) ? w_v[k*D_DIM + n] : w_g[k*D_DIM + (n - D_DIM)];
    g_wt16[n*64 + k] = __float2half_rn(val);
}

// ============================================================
// Kernel 0b: transpose+split w_o -> g_woth/g_wotl [n=64][k=256]
// ============================================================
__global__ void k_prep_wo(const float* __restrict__ w_o)
{
    int n = blockIdx.x, k = threadIdx.x;   // 64 blocks x 256 threads
    float val = w_o[k*CIN + n];
    __half hi = __float2half_rn(val);
    __half lo = __float2half_rn(val - __half2float(hi));
    g_woth[n*256 + k] = hi;
    g_wotl[n*256 + k] = lo;
}

// ============================================================
// Kernel 1: LN(z) + logits (warp per (q,k) row)
// ============================================================
__global__ void k_lnz_logits(const float* __restrict__ z, const float* __restrict__ mask,
                             const float* __restrict__ gamma_z, const float* __restrict__ beta_z,
                             const float* __restrict__ w_z, const float* __restrict__ b_z)
{
    int gw   = (blockIdx.x * blockDim.x + threadIdx.x) >> 5;
    int lane = threadIdx.x & 31;
    if (gw >= N_DIM * N_DIM) return;
    int q = gw / N_DIM, k = gw % N_DIM;
    const float* zp = z + (size_t)gw * CZ;

    float x0 = zp[lane], x1 = zp[lane+32], x2 = zp[lane+64], x3 = zp[lane+96];
    float s  = x0+x1+x2+x3;
    float s2 = x0*x0 + x1*x1 + x2*x2 + x3*x3;
    #pragma unroll
    for (int o = 16; o; o >>= 1) {
        s  += __shfl_xor_sync(0xffffffffu, s,  o);
        s2 += __shfl_xor_sync(0xffffffffu, s2, o);
    }
    float mu  = s * (1.0f / CZ);
    float inv = rsqrtf(s2 * (1.0f / CZ) - mu*mu + EPS_);
    float n0 = (x0-mu)*inv*gamma_z[lane]    + beta_z[lane];
    float n1 = (x1-mu)*inv*gamma_z[lane+32] + beta_z[lane+32];
    float n2 = (x2-mu)*inv*gamma_z[lane+64] + beta_z[lane+64];
    float n3 = (x3-mu)*inv*gamma_z[lane+96] + beta_z[lane+96];

    float acc[H_DIM];
    #pragma unroll
    for (int h = 0; h < H_DIM; h++) {
        acc[h] = n0 * w_z[lane*H_DIM + h]
               + n1 * w_z[(lane+32)*H_DIM + h]
               + n2 * w_z[(lane+64)*H_DIM + h]
               + n3 * w_z[(lane+96)*H_DIM + h];
        #pragma unroll
        for (int o = 16; o; o >>= 1)
            acc[h] += __shfl_xor_sync(0xffffffffu, acc[h], o);
    }
    if (lane == 0) {
        float bias = INF_ * (mask[gw] - 1.0f);
        #pragma unroll
        for (int h = 0; h < H_DIM; h++)
            g_w[((size_t)h*N_DIM + q)*N_DIM + k] = acc[h] + b_z[h] + bias;
    }
}

// ============================================================
// Kernel 2: softmax per (h,q) row -> single-fp16 staging (k-major)
// ============================================================
__global__ void k_softmax()
{
    int row = blockIdx.x;                   // h*384 + q
    int h = row / N_DIM, q = row - h*N_DIM;
    const float* p = g_w + (size_t)row * N_DIM;
    int tid = threadIdx.x;                  // 128 threads, 3 elems each
    __shared__ float red[128];

    float v0 = p[tid], v1 = p[tid+128], v2 = p[tid+256];
    float mx = fmaxf(v0, fmaxf(v1, v2));
    red[tid] = mx; __syncthreads();
    for (int o = 64; o; o >>= 1) { if (tid < o) red[tid] = fmaxf(red[tid], red[tid+o]); __syncthreads(); }
    mx = red[0]; __syncthreads();

    float e0 = expf(v0-mx), e1 = expf(v1-mx), e2 = expf(v2-mx);
    red[tid] = e0 + e1 + e2; __syncthreads();
    for (int o = 64; o; o >>= 1) { if (tid < o) red[tid] += red[tid+o]; __syncthreads(); }
    float inv = 1.0f / red[0];

    int r = q & 127;
    size_t blkbase = (size_t)((h*3 + (q >> 7)) * NKC);
    float ev[3] = {e0, e1, e2};
    #pragma unroll
    for (int t = 0; t < 3; t++) {
        int k = tid + t*128;
        float wv = ev[t] * inv;
        int kc = k >> 6, kk = k & 63;
        size_t off = (blkbase + kc) * 8192 + (size_t)(r*64 + kk);
        g_wh[off] = __float2half_rn(wv);
    }
}

// ============================================================
// Kernel 3: LN(m) -> single-fp16 mn (k-major rows of 64)
// ============================================================
__global__ void k_lnm(const float* __restrict__ m,
                      const float* __restrict__ gamma_m, const float* __restrict__ beta_m)
{
    int gw   = (blockIdx.x * blockDim.x + threadIdx.x) >> 5;
    int lane = threadIdx.x & 31;
    if (gw >= MROWS) return;
    const float* mp = m + (size_t)gw * CIN;
    float a = mp[lane], b = mp[lane+32];
    float s = a + b, s2 = a*a + b*b;
    #pragma unroll
    for (int o = 16; o; o >>= 1) {
        s  += __shfl_xor_sync(0xffffffffu, s,  o);
        s2 += __shfl_xor_sync(0xffffffffu, s2, o);
    }
    float mu  = s * (1.0f / CIN);
    float inv = rsqrtf(s2 * (1.0f / CIN) - mu*mu + EPS_);
    float na = (a-mu)*inv*gamma_m[lane]    + beta_m[lane];
    float nb = (b-mu)*inv*gamma_m[lane+32] + beta_m[lane+32];
    size_t base = (size_t)gw * CIN;
    g_mn16[base + lane]      = __float2half_rn(na);
    g_mn16[base + lane + 32] = __float2half_rn(nb);
}

// ============================================================
// Kernel 4: v/gate projection via mma.sync SINGLE fp16
//   grid (4, 1536); A 16KB + B 16KB operands, fp16 T (35KB)
//   n0<256: v -> fp16 T-transpose -> staging
//   n0>=256: gate -> sigmoid -> g_g (fp16)
// ============================================================
__global__ __launch_bounds__(256) void k_gemm_vg_mma(const float* __restrict__ b_v,
                                                     const float* __restrict__ b_g)
{
    extern __shared__ __align__(128) char smem[];
    int tid = threadIdx.x;
    int n0 = blockIdx.x * 128;
    int m0 = blockIdx.y * 128;
    int wid = tid >> 5, lane = tid & 31;
    int warpM = wid >> 2, warpN = wid & 3;
    uint32_t sbase = smem_u32(smem);
    uint32_t sA = sbase, sB = sbase + 16384;

    const char* aSrc = (const char*)(g_mn16 + (size_t)m0*64);
    const char* bSrc = (const char*)(g_wt16 + (size_t)n0*64);

    #pragma unroll
    for (int u = 0; u < 8; u++) {
        int idx = u*256 + tid;              // 0..2047
        int tile = idx >> 10;
        uint32_t x = (uint32_t)(idx & 1023) * 16;
        uint32_t dst = (tile ? sB : sA) + (x ^ ((x >> 3) & 0x70));
        cpasync16(dst, (tile ? bSrc : aSrc) + x);
    }
    asm volatile("cp.async.commit_group;" ::: "memory");
    asm volatile("cp.async.wait_group 0;" ::: "memory");
    __syncthreads();

    float acc[4][4][4] = {};
    #pragma unroll
    for (int kt = 0; kt < 4; kt++) {
        uint32_t a[4][4], b[4][2];
        #pragma unroll
        for (int mt = 0; mt < 4; mt++) {
            int row = warpM*64 + mt*16 + (lane & 15);
            uint32_t x = (uint32_t)row*128 + kt*32 + ((lane >> 4)*16);
            uint32_t sw = x ^ ((x >> 3) & 0x70);
            LDSM_X4(a[mt][0], a[mt][1], a[mt][2], a[mt][3], sA + sw);
        }
        #pragma unroll
        for (int p = 0; p < 2; p++) {
            int g = lane >> 3;
            int ntile = p*2 + (g >> 1);
            int row = warpN*32 + ntile*8 + (lane & 7);
            uint32_t x = (uint32_t)row*128 + kt*32 + (g & 1)*16;
            uint32_t sw = x ^ ((x >> 3) & 0x70);
            uint32_t r[4];
            LDSM_X4(r[0], r[1], r[2], r[3], sB + sw);
            b[p*2][0] = r[0]; b[p*2][1] = r[1];
            b[p*2+1][0] = r[2]; b[p*2+1][1] = r[3];
        }
        #pragma unroll
        for (int mt = 0; mt < 4; mt++)
            #pragma unroll
            for (int nn = 0; nn < 4; nn++)
                mma_fp16(acc[mt][nn], a[mt], b[nn]);
    }
    __syncthreads();

    if (n0 < D_DIM) {
        // ---- v: fp16 transpose buffer T[(col*2+kcl)*68 + kk] ----
        __half* T = (__half*)smem;    // 256*68 halves = 34816 B
        #pragma unroll
        for (int mt = 0; mt < 4; mt++) {
            int qr = warpM*64 + mt*16 + (lane >> 2);
            int qr2 = qr + 8;
            #pragma unroll
            for (int nn = 0; nn < 4; nn++) {
                int nc = warpN*32 + nn*8 + (lane & 3)*2;
                float bv0 = b_v[n0 + nc], bv1 = b_v[n0 + nc + 1];
                T[((nc  )*2 + (qr  >> 6))*68 + (qr  & 63)] = __float2half_rn(acc[mt][nn][0] + bv0);
                T[((nc+1)*2 + (qr  >> 6))*68 + (qr  & 63)] = __float2half_rn(acc[mt][nn][1] + bv1);
                T[((nc  )*2 + (qr2 >> 6))*68 + (qr2 & 63)] = __float2half_rn(acc[mt][nn][2] + bv0);
                T[((nc+1)*2 + (qr2 >> 6))*68 + (qr2 & 63)] = __float2half_rn(acc[mt][nn][3] + bv1);
            }
        }
        __syncthreads();

        int sI = m0 / N_DIM;
        int kb = m0 - sI * N_DIM;
        int nt = sI >> 2;
        int j   = tid >> 1, kcl = tid & 1;
        int col = n0 + j;
        int h   = col >> 5, c = col & 31;
        int nr  = ((sI & 3) << 5) + c;
        int kc  = (kb >> 6) + kcl;
        size_t blk = ((size_t)(h*128 + nt)*NKC + kc) * 8192;
        const __half* Tr = T + (j*2 + kcl)*68;
        #pragma unroll
        for (int kk = 0; kk < 64; kk += 2) {
            *(__half2*)&g_vh[blk + (size_t)nr*64 + kk] = *(const __half2*)&Tr[kk];
        }
    } else {
        int jb = n0 - D_DIM;
        #pragma unroll
        for (int mt = 0; mt < 4; mt++) {
            int row = m0 + warpM*64 + mt*16 + (lane >> 2);
            #pragma unroll
            for (int nn = 0; nn < 4; nn++) {
                int jg = jb + warpN*32 + nn*8 + (lane & 3)*2;
                float bg0 = b_g[jg], bg1 = b_g[jg+1];
                float t0 = acc[mt][nn][0] + bg0, t1 = acc[mt][nn][1] + bg1;
                float t2 = acc[mt][nn][2] + bg0, t3 = acc[mt][nn][3] + bg1;
                *(__half2*)&g_g[(size_t)row*D_DIM + jg] =
                    __floats2half2_rn(1.0f/(1.0f+expf(-t0)), 1.0f/(1.0f+expf(-t1)));
                *(__half2*)&g_g[(size_t)(row+8)*D_DIM + jg] =
                    __floats2half2_rn(1.0f/(1.0f+expf(-t2)), 1.0f/(1.0f+expf(-t3)));
            }
        }
    }
}

// ============================================================
// Kernel 5: attention GEMM, SINGLE fp16 operands, 64x64 warp
//   tiles (BM=128, BN=256); stage = A 16KB + B 32KB, x2 stages
// ============================================================
__global__ __launch_bounds__(256, 1) void k_gemm_att_mma()
{
    extern __shared__ __align__(128) char smem[];
    const uint32_t STAGE = 49152;
    int tid = threadIdx.x;
    int qt = blockIdx.x, nt = blockIdx.y, h = blockIdx.z;
    int wid = tid >> 5, lane = tid & 31;
    int warpM = wid >> 2, warpN = wid & 3;
    uint32_t sbase = smem_u32(smem);

    const char* aH  = (const char*)(g_wh + (size_t)(h*3   + qt) * NKC * 8192);
    const char* bH0 = (const char*)(g_vh + (size_t)(h*128 + nt*2    ) * NKC * 8192);
    const char* bH1 = (const char*)(g_vh + (size_t)(h*128 + nt*2 + 1) * NKC * 8192);

    float acc[4][8][4] = {};

    auto load_chunk = [&](int kc, int stage){
        size_t cb = (size_t)kc * 16384;
        #pragma unroll
        for (int t = 0; t < 12; t++) {
            int tile = t >> 2;                   // 3 tiles of 16KB
            int c    = (t & 3) * 256 + tid;
            uint32_t x = (uint32_t)c * 16;
            uint32_t dst = sbase + stage*STAGE + (uint32_t)tile*16384
                         + (x ^ ((x >> 3) & 0x70));
            const char* src = (tile == 0 ? aH : tile == 1 ? bH0 : bH1) + cb + x;
            cpasync16(dst, src);
        }
        asm volatile("cp.async.commit_group;" ::: "memory");
    };

    load_chunk(0, 0);
    for (int kc = 0; kc < NKC; kc++) {
        int stage = kc & 1;
        if (kc < NKC-1) load_chunk(kc+1, stage ^ 1);
        if (kc < NKC-1) asm volatile("cp.async.wait_group 1;" ::: "memory");
        else            asm volatile("cp.async.wait_group 0;" ::: "memory");
        __syncthreads();

        uint32_t sA = sbase + stage*STAGE;
        uint32_t sB = sA + 16384;            // 32KB: rows 0..255

        #pragma unroll
        for (int kt = 0; kt < 4; kt++) {
            uint32_t a[4][4], b[8][2];
            #pragma unroll
            for (int mt = 0; mt < 4; mt++) {
                int row = warpM*64 + mt*16 + (lane & 15);
                uint32_t x = (uint32_t)row*128 + kt*32 + ((lane >> 4)*16);
                uint32_t sw = x ^ ((x >> 3) & 0x70);
                LDSM_X4(a[mt][0], a[mt][1], a[mt][2], a[mt][3], sA + sw);
            }
            #pragma unroll
            for (int bh = 0; bh < 2; bh++) {
                #pragma unroll
                for (int p = 0; p < 2; p++) {
                    int g = lane >> 3;
                    int ntl = p*2 + (g >> 1);
                    int row = warpN*64 + bh*32 + ntl*8 + (lane & 7);
                    uint32_t x = (uint32_t)row*128 + kt*32 + (g & 1)*16;
                    uint32_t sw = x ^ ((x >> 3) & 0x70);
                    uint32_t r[4];
                    LDSM_X4(r[0], r[1], r[2], r[3], sB + sw);
                    b[bh*4 + p*2    ][0] = r[0]; b[bh*4 + p*2    ][1] = r[1];
                    b[bh*4 + p*2 + 1][0] = r[2]; b[bh*4 + p*2 + 1][1] = r[3];
                }
            }
            #pragma unroll
            for (int mt = 0; mt < 4; mt++)
                #pragma unroll
                for (int nn = 0; nn < 8; nn++)
                    mma_fp16(acc[mt][nn], a[mt], b[nn]);
        }
        __syncthreads();
    }

    // ---- epilogue: fp16 stores into g_o[(s*384+q)*256 + h*32 + c] ----
    #pragma unroll
    for (int mt = 0; mt < 4; mt++) {
        int q = qt*128 + warpM*64 + mt*16 + (lane >> 2);
        #pragma unroll
        for (int nn = 0; nn < 8; nn++) {
            int n = nt*256 + warpN*64 + (nn >> 2)*32 + (nn & 3)*8 + (lane & 3)*2;
            int s = n >> 5, c = n & 31;
            size_t b0 = ((size_t)s*N_DIM + q    )*D_DIM + h*C_DIM + c;
            size_t b1 = ((size_t)s*N_DIM + q + 8)*D_DIM + h*C_DIM + c;
            *(__half2*)&g_o[b0] = __floats2half2_rn(acc[mt][nn][0], acc[mt][nn][1]);
            *(__half2*)&g_o[b1] = __floats2half2_rn(acc[mt][nn][2], acc[mt][nn][3]);
        }
    }
}

// ============================================================
// Kernel 6: output projection via mma.sync fp16 (3-term split)
// ============================================================
__global__ __launch_bounds__(256, 2) void k_gemm_out_mma(const float* __restrict__ b_o,
                                                         float* __restrict__ out)
{
    __shared__ __align__(128) char smem[49152];
    uint32_t sbase = smem_u32(smem);
    uint32_t sAh = sbase, sAl = sbase + 16384, sBh = sbase + 32768, sBl = sbase + 40960;
    int tid = threadIdx.x;
    int m0  = blockIdx.x * 128;
    int wid = tid >> 5, lane = tid & 31;
    int warpM = wid >> 1, warpN = wid & 1;

    float acc[2][4][4] = {};
    int arow = tid >> 1, ahalf = tid & 1;

    for (int k0 = 0; k0 < D_DIM; k0 += 64) {
        #pragma unroll
        for (int u = 0; u < 4; u++) {
            int idx = u*256 + tid;
            int tile = idx >> 9, rem = idx & 511;
            int n = rem >> 3, j = rem & 7;
            uint32_t x = (uint32_t)n*128 + j*16;
            uint32_t dst = (tile ? sBl : sBh) + (x ^ ((x >> 3) & 0x70));
            const __half* src = (tile ? g_wotl : g_woth) + n*256 + k0 + j*8;
            cpasync16(dst, src);
        }
        asm volatile("cp.async.commit_group;" ::: "memory");

        {
            size_t base = (size_t)(m0 + arow)*D_DIM + k0 + ahalf*32;
            uint32_t xb = (uint32_t)arow*128 + ahalf*64;
            #pragma unroll
            for (int u = 0; u < 4; u++) {
                uint4 ov = *(const uint4*)(g_o + base + u*8);
                uint4 gv = *(const uint4*)(g_g + base + u*8);
                const __half2* po = (const __half2*)&ov;
                const __half2* pg = (const __half2*)&gv;
                uint4 hv, lv;
                uint32_t* ph = (uint32_t*)&hv;
                uint32_t* pl = (uint32_t*)&lv;
                #pragma unroll
                for (int j = 0; j < 4; j++) {
                    float2 fo = __half22float2(po[j]);
                    float2 fg = __half22float2(pg[j]);
                    float p0 = fo.x * fg.x, p1 = fo.y * fg.y;
                    __half2 hh = __floats2half2_rn(p0, p1);
                    float2 hf = __half22float2(hh);
                    __half2 ll = __floats2half2_rn(p0 - hf.x, p1 - hf.y);
                    ph[j] = *(uint32_t*)&hh;
                    pl[j] = *(uint32_t*)&ll;
                }
                uint32_t x = xb + u*16;
                uint32_t sw = x ^ ((x >> 3) & 0x70);
                *(uint4*)(smem + sw)         = hv;
                *(uint4*)(smem + 16384 + sw) = lv;
            }
        }
        asm volatile("cp.async.wait_group 0;" ::: "memory");
        __syncthreads();

        #pragma unroll
        for (int kt = 0; kt < 4; kt++) {
            uint32_t a_hi[2][4], a_lo[2][4], b_hi[4][2], b_lo[4][2];
            #pragma unroll
            for (int mt = 0; mt < 2; mt++) {
                int row = warpM*32 + mt*16 + (lane & 15);
                uint32_t x = (uint32_t)row*128 + kt*32 + ((lane >> 4)*16);
                uint32_t sw = x ^ ((x >> 3) & 0x70);
                LDSM_X4(a_hi[mt][0], a_hi[mt][1], a_hi[mt][2], a_hi[mt][3], sAh + sw);
                LDSM_X4(a_lo[mt][0], a_lo[mt][1], a_lo[mt][2], a_lo[mt][3], sAl + sw);
            }
            #pragma unroll
            for (int p = 0; p < 2; p++) {
                int g = lane >> 3;
                int ntile = p*2 + (g >> 1);
                int row = warpN*32 + ntile*8 + (lane & 7);
                uint32_t x = (uint32_t)row*128 + kt*32 + (g & 1)*16;
                uint32_t sw = x ^ ((x >> 3) & 0x70);
                uint32_t r[4];
                LDSM_X4(r[0], r[1], r[2], r[3], sBh + sw);
                b_hi[p*2][0] = r[0]; b_hi[p*2][1] = r[1];
                b_hi[p*2+1][0] = r[2]; b_hi[p*2+1][1] = r[3];
                LDSM_X4(r[0], r[1], r[2], r[3], sBl + sw);
                b_lo[p*2][0] = r[0]; b_lo[p*2][1] = r[1];
                b_lo[p*2+1][0] = r[2]; b_lo[p*2+1][1] = r[3];
            }
            #pragma unroll
            for (int mt = 0; mt < 2; mt++)
                #pragma unroll
                for (int nn = 0; nn < 4; nn++)
                    mma_fp16(acc[mt][nn], a_hi[mt], b_hi[nn]);
            #pragma unroll
            for (int mt = 0; mt < 2; mt++)
                #pragma unroll
                for (int nn = 0; nn < 4; nn++)
                    mma_fp16(acc[mt][nn], a_lo[mt], b_hi[nn]);
            #pragma unroll
            for (int mt = 0; mt < 2; mt++)
                #pragma unroll
                for (int nn = 0; nn < 4; nn++)
                    mma_fp16(acc[mt][nn], a_hi[mt], b_lo[nn]);
        }
        __syncthreads();
    }

    #pragma unroll
    for (int mt = 0; mt < 2; mt++) {
        int row = m0 + warpM*32 + mt*16 + (lane >> 2);
        #pragma unroll
        for (int nn = 0; nn < 4; nn++) {
            int col = warpN*32 + nn*8 + (lane & 3)*2;
            float b0 = b_o[col], b1 = b_o[col+1];
            *(float2*)(out + (size_t)row*CIN + col) =
                make_float2(acc[mt][nn][0] + b0, acc[mt][nn][1] + b1);
            *(float2*)(out + (size_t)(row+8)*CIN + col) =
                make_float2(acc[mt][nn][2] + b0, acc[mt][nn][3] + b1);
        }
    }
}

// ============================================================
extern "C" void kernel_launch(void* const* d_in, const int* in_sizes, int n_in,
                              void* d_out, int out_size)
{
    const float* m       = (const float*)d_in[0];
    const float* z       = (const float*)d_in[1];
    const float* mask    = (const float*)d_in[2];
    const float* gamma_m = (const float*)d_in[3];
    const float* beta_m  = (const float*)d_in[4];
    const float* gamma_z = (const float*)d_in[5];
    const float* beta_z  = (const float*)d_in[6];
    const float* w_z     = (const float*)d_in[7];
    const float* b_z     = (const float*)d_in[8];
    const float* w_v     = (const float*)d_in[9];
    const float* b_v     = (const float*)d_in[10];
    const float* w_g     = (const float*)d_in[11];
    const float* b_g     = (const float*)d_in[12];
    const float* w_o     = (const float*)d_in[13];
    const float* b_o     = (const float*)d_in[14];
    float* out = (float*)d_out;

    cudaFuncSetAttribute(k_gemm_att_mma, cudaFuncAttributeMaxDynamicSharedMemorySize, 98304);
    cudaFuncSetAttribute(k_gemm_vg_mma,  cudaFuncAttributeMaxDynamicSharedMemorySize, 34816);

    k_prep_w<<<512, 64>>>(w_v, w_g);
    k_prep_wo<<<64, 256>>>(w_o);
    k_lnz_logits<<<(N_DIM*N_DIM)/8, 256>>>(z, mask, gamma_z, beta_z, w_z, b_z);
    k_softmax<<<H_DIM*N_DIM, 128>>>();
    k_lnm<<<MROWS/8, 256>>>(m, gamma_m, beta_m);
    k_gemm_vg_mma<<<dim3(4, MROWS/128), 256, 34816>>>(b_v, b_g);
    k_gemm_att_mma<<<dim3(3, 64, 8), 256, 98304>>>();
    k_gemm_out_mma<<<MROWS/128, 256>>>(b_o, out);
}

// round 16
// speedup vs baseline: 1.6115x; 1.0391x over previous
#include <cuda_runtime.h>
#include <cuda_bf16.h>
#include <cuda_fp16.h>
#include <math.h>
#include <stdint.h>

#define S_DIM 512
#define N_DIM 384
#define CIN   64
#define CZ    128
#define H_DIM 8
#define C_DIM 32
#define D_DIM 256
#define INF_  1e9f
#define EPS_  1e-5f
#define MROWS (S_DIM*N_DIM)   // 196608
#define NKC   6               // K chunks of 64 covering K=384

// ---- scratch (static device arrays: no allocations allowed) ----
__device__ float g_w [(size_t)H_DIM*N_DIM*N_DIM];   // logits [h][q][k]
__device__ __half g_g [(size_t)MROWS*D_DIM];        // gate (fp16)
__device__ __half g_o [(size_t)MROWS*D_DIM];        // attention output (fp16)
// LN(m) single-fp16, k-major rows of 64 (128B rows)
__device__ __align__(1024) __half g_mn16[(size_t)MROWS*CIN];
// transposed [n=512][k=64] single-fp16 weights (w_v | w_g)
__device__ __align__(1024) __half g_wt16[512*64];
// transposed [n=64][k=256] single-fp16 w_o
__device__ __align__(1024) __half g_wot16[64*256];
// SINGLE-fp16 k-major staging tiles, 128 rows x 64 k each (8192 elems, 16KB)
// w: [h][qt(3)][kc(6)]   v: [h][nt(128)][kc(6)]
__device__ __align__(1024) __half g_wh[(size_t)H_DIM*3*NKC*8192];
__device__ __align__(1024) __half g_vh[(size_t)H_DIM*128*NKC*8192];

// ============================================================
// helpers (Ampere-class ISA only: valid on base sm_103 target)
// ============================================================
__device__ __forceinline__ uint32_t smem_u32(const void* p){
    uint32_t a;
    asm("{ .reg .u64 t; cvta.to.shared.u64 t, %1; cvt.u32.u64 %0, t; }" : "=r"(a) : "l"(p));
    return a;
}
#define LDSM_X4(r0,r1,r2,r3,addr) \
    asm volatile("ldmatrix.sync.aligned.m8n8.x4.shared.b16 {%0,%1,%2,%3}, [%4];" \
        : "=r"(r0),"=r"(r1),"=r"(r2),"=r"(r3) : "r"(addr))
__device__ __forceinline__ void mma_fp16(float* c, const uint32_t* a, const uint32_t* b){
    asm volatile("mma.sync.aligned.m16n8k16.row.col.f32.f16.f16.f32 "
        "{%0,%1,%2,%3}, {%4,%5,%6,%7}, {%8,%9}, {%0,%1,%2,%3};"
        : "+f"(c[0]),"+f"(c[1]),"+f"(c[2]),"+f"(c[3])
        : "r"(a[0]),"r"(a[1]),"r"(a[2]),"r"(a[3]), "r"(b[0]),"r"(b[1]));
}
__device__ __forceinline__ void cpasync16(uint32_t dst, const void* src){
    asm volatile("cp.async.cg.shared.global [%0], [%1], 16;" :: "r"(dst), "l"(src));
}

// ============================================================
// Kernel 0a: transpose weights -> g_wt16 [n=512][k=64] (fp16)
// ============================================================
__global__ void k_prep_w(const float* __restrict__ w_v, const float* __restrict__ w_g)
{
    int n = blockIdx.x, k = threadIdx.x;   // 512 blocks x 64 threads
    float val = (n < D_DIM) ? w_v[k*D_DIM + n] : w_g[k*D_DIM + (n - D_DIM)];
    g_wt16[n*64 + k] = __float2half_rn(val);
}

// ============================================================
// Kernel 0b: transpose w_o -> g_wot16 [n=64][k=256] (fp16)
// ============================================================
__global__ void k_prep_wo(const float* __restrict__ w_o)
{
    int n = blockIdx.x, k = threadIdx.x;   // 64 blocks x 256 threads
    g_wot16[n*256 + k] = __float2half_rn(w_o[k*CIN + n]);
}

// ============================================================
// Kernel 1: LN(z) + logits (warp per (q,k) row)
// ============================================================
__global__ void k_lnz_logits(const float* __restrict__ z, const float* __restrict__ mask,
                             const float* __restrict__ gamma_z, const float* __restrict__ beta_z,
                             const float* __restrict__ w_z, const float* __restrict__ b_z)
{
    int gw   = (blockIdx.x * blockDim.x + threadIdx.x) >> 5;
    int lane = threadIdx.x & 31;
    if (gw >= N_DIM * N_DIM) return;
    int q = gw / N_DIM, k = gw % N_DIM;
    const float* zp = z + (size_t)gw * CZ;

    float x0 = zp[lane], x1 = zp[lane+32], x2 = zp[lane+64], x3 = zp[lane+96];
    float s  = x0+x1+x2+x3;
    float s2 = x0*x0 + x1*x1 + x2*x2 + x3*x3;
    #pragma unroll
    for (int o = 16; o; o >>= 1) {
        s  += __shfl_xor_sync(0xffffffffu, s,  o);
        s2 += __shfl_xor_sync(0xffffffffu, s2, o);
    }
    float mu  = s * (1.0f / CZ);
    float inv = rsqrtf(s2 * (1.0f / CZ) - mu*mu + EPS_);
    float n0 = (x0-mu)*inv*gamma_z[lane]    + beta_z[lane];
    float n1 = (x1-mu)*inv*gamma_z[lane+32] + beta_z[lane+32];
    float n2 = (x2-mu)*inv*gamma_z[lane+64] + beta_z[lane+64];
    float n3 = (x3-mu)*inv*gamma_z[lane+96] + beta_z[lane+96];

    float acc[H_DIM];
    #pragma unroll
    for (int h = 0; h < H_DIM; h++) {
        acc[h] = n0 * w_z[lane*H_DIM + h]
               + n1 * w_z[(lane+32)*H_DIM + h]
               + n2 * w_z[(lane+64)*H_DIM + h]
               + n3 * w_z[(lane+96)*H_DIM + h];
        #pragma unroll
        for (int o = 16; o; o >>= 1)
            acc[h] += __shfl_xor_sync(0xffffffffu, acc[h], o);
    }
    if (lane == 0) {
        float bias = INF_ * (mask[gw] - 1.0f);
        #pragma unroll
        for (int h = 0; h < H_DIM; h++)
            g_w[((size_t)h*N_DIM + q)*N_DIM + k] = acc[h] + b_z[h] + bias;
    }
}

// ============================================================
// Kernel 2: softmax per (h,q) row -> single-fp16 staging (k-major)
// ============================================================
__global__ void k_softmax()
{
    int row = blockIdx.x;                   // h*384 + q
    int h = row / N_DIM, q = row - h*N_DIM;
    const float* p = g_w + (size_t)row * N_DIM;
    int tid = threadIdx.x;                  // 128 threads, 3 elems each
    __shared__ float red[128];

    float v0 = p[tid], v1 = p[tid+128], v2 = p[tid+256];
    float mx = fmaxf(v0, fmaxf(v1, v2));
    red[tid] = mx; __syncthreads();
    for (int o = 64; o; o >>= 1) { if (tid < o) red[tid] = fmaxf(red[tid], red[tid+o]); __syncthreads(); }
    mx = red[0]; __syncthreads();

    float e0 = expf(v0-mx), e1 = expf(v1-mx), e2 = expf(v2-mx);
    red[tid] = e0 + e1 + e2; __syncthreads();
    for (int o = 64; o; o >>= 1) { if (tid < o) red[tid] += red[tid+o]; __syncthreads(); }
    float inv = 1.0f / red[0];

    int r = q & 127;
    size_t blkbase = (size_t)((h*3 + (q >> 7)) * NKC);
    float ev[3] = {e0, e1, e2};
    #pragma unroll
    for (int t = 0; t < 3; t++) {
        int k = tid + t*128;
        float wv = ev[t] * inv;
        int kc = k >> 6, kk = k & 63;
        size_t off = (blkbase + kc) * 8192 + (size_t)(r*64 + kk);
        g_wh[off] = __float2half_rn(wv);
    }
}

// ============================================================
// Kernel 3: LN(m) -> single-fp16 mn (k-major rows of 64)
// ============================================================
__global__ void k_lnm(const float* __restrict__ m,
                      const float* __restrict__ gamma_m, const float* __restrict__ beta_m)
{
    int gw   = (blockIdx.x * blockDim.x + threadIdx.x) >> 5;
    int lane = threadIdx.x & 31;
    if (gw >= MROWS) return;
    const float* mp = m + (size_t)gw * CIN;
    float a = mp[lane], b = mp[lane+32];
    float s = a + b, s2 = a*a + b*b;
    #pragma unroll
    for (int o = 16; o; o >>= 1) {
        s  += __shfl_xor_sync(0xffffffffu, s,  o);
        s2 += __shfl_xor_sync(0xffffffffu, s2, o);
    }
    float mu  = s * (1.0f / CIN);
    float inv = rsqrtf(s2 * (1.0f / CIN) - mu*mu + EPS_);
    float na = (a-mu)*inv*gamma_m[lane]    + beta_m[lane];
    float nb = (b-mu)*inv*gamma_m[lane+32] + beta_m[lane+32];
    size_t base = (size_t)gw * CIN;
    g_mn16[base + lane]      = __float2half_rn(na);
    g_mn16[base + lane + 32] = __float2half_rn(nb);
}

// ============================================================
// Kernel 4: v/gate projection via mma.sync SINGLE fp16
//   grid (4, 1536); A 16KB + B 16KB operands, fp16 T (35KB)
// ============================================================
__global__ __launch_bounds__(256) void k_gemm_vg_mma(const float* __restrict__ b_v,
                                                     const float* __restrict__ b_g)
{
    extern __shared__ __align__(128) char smem[];
    int tid = threadIdx.x;
    int n0 = blockIdx.x * 128;
    int m0 = blockIdx.y * 128;
    int wid = tid >> 5, lane = tid & 31;
    int warpM = wid >> 2, warpN = wid & 3;
    uint32_t sbase = smem_u32(smem);
    uint32_t sA = sbase, sB = sbase + 16384;

    const char* aSrc = (const char*)(g_mn16 + (size_t)m0*64);
    const char* bSrc = (const char*)(g_wt16 + (size_t)n0*64);

    #pragma unroll
    for (int u = 0; u < 8; u++) {
        int idx = u*256 + tid;              // 0..2047
        int tile = idx >> 10;
        uint32_t x = (uint32_t)(idx & 1023) * 16;
        uint32_t dst = (tile ? sB : sA) + (x ^ ((x >> 3) & 0x70));
        cpasync16(dst, (tile ? bSrc : aSrc) + x);
    }
    asm volatile("cp.async.commit_group;" ::: "memory");
    asm volatile("cp.async.wait_group 0;" ::: "memory");
    __syncthreads();

    float acc[4][4][4] = {};
    #pragma unroll
    for (int kt = 0; kt < 4; kt++) {
        uint32_t a[4][4], b[4][2];
        #pragma unroll
        for (int mt = 0; mt < 4; mt++) {
            int row = warpM*64 + mt*16 + (lane & 15);
            uint32_t x = (uint32_t)row*128 + kt*32 + ((lane >> 4)*16);
            uint32_t sw = x ^ ((x >> 3) & 0x70);
            LDSM_X4(a[mt][0], a[mt][1], a[mt][2], a[mt][3], sA + sw);
        }
        #pragma unroll
        for (int p = 0; p < 2; p++) {
            int g = lane >> 3;
            int ntile = p*2 + (g >> 1);
            int row = warpN*32 + ntile*8 + (lane & 7);
            uint32_t x = (uint32_t)row*128 + kt*32 + (g & 1)*16;
            uint32_t sw = x ^ ((x >> 3) & 0x70);
            uint32_t r[4];
            LDSM_X4(r[0], r[1], r[2], r[3], sB + sw);
            b[p*2][0] = r[0]; b[p*2][1] = r[1];
            b[p*2+1][0] = r[2]; b[p*2+1][1] = r[3];
        }
        #pragma unroll
        for (int mt = 0; mt < 4; mt++)
            #pragma unroll
            for (int nn = 0; nn < 4; nn++)
                mma_fp16(acc[mt][nn], a[mt], b[nn]);
    }
    __syncthreads();

    if (n0 < D_DIM) {
        // ---- v: fp16 transpose buffer T[(col*2+kcl)*68 + kk] ----
        __half* T = (__half*)smem;    // 256*68 halves = 34816 B
        #pragma unroll
        for (int mt = 0; mt < 4; mt++) {
            int qr = warpM*64 + mt*16 + (lane >> 2);
            int qr2 = qr + 8;
            #pragma unroll
            for (int nn = 0; nn < 4; nn++) {
                int nc = warpN*32 + nn*8 + (lane & 3)*2;
                float bv0 = b_v[n0 + nc], bv1 = b_v[n0 + nc + 1];
                T[((nc  )*2 + (qr  >> 6))*68 + (qr  & 63)] = __float2half_rn(acc[mt][nn][0] + bv0);
                T[((nc+1)*2 + (qr  >> 6))*68 + (qr  & 63)] = __float2half_rn(acc[mt][nn][1] + bv1);
                T[((nc  )*2 + (qr2 >> 6))*68 + (qr2 & 63)] = __float2half_rn(acc[mt][nn][2] + bv0);
                T[((nc+1)*2 + (qr2 >> 6))*68 + (qr2 & 63)] = __float2half_rn(acc[mt][nn][3] + bv1);
            }
        }
        __syncthreads();

        int sI = m0 / N_DIM;
        int kb = m0 - sI * N_DIM;
        int nt = sI >> 2;
        int j   = tid >> 1, kcl = tid & 1;
        int col = n0 + j;
        int h   = col >> 5, c = col & 31;
        int nr  = ((sI & 3) << 5) + c;
        int kc  = (kb >> 6) + kcl;
        size_t blk = ((size_t)(h*128 + nt)*NKC + kc) * 8192;
        const __half* Tr = T + (j*2 + kcl)*68;
        #pragma unroll
        for (int kk = 0; kk < 64; kk += 2) {
            *(__half2*)&g_vh[blk + (size_t)nr*64 + kk] = *(const __half2*)&Tr[kk];
        }
    } else {
        int jb = n0 - D_DIM;
        #pragma unroll
        for (int mt = 0; mt < 4; mt++) {
            int row = m0 + warpM*64 + mt*16 + (lane >> 2);
            #pragma unroll
            for (int nn = 0; nn < 4; nn++) {
                int jg = jb + warpN*32 + nn*8 + (lane & 3)*2;
                float bg0 = b_g[jg], bg1 = b_g[jg+1];
                float t0 = acc[mt][nn][0] + bg0, t1 = acc[mt][nn][1] + bg1;
                float t2 = acc[mt][nn][2] + bg0, t3 = acc[mt][nn][3] + bg1;
                *(__half2*)&g_g[(size_t)row*D_DIM + jg] =
                    __floats2half2_rn(1.0f/(1.0f+expf(-t0)), 1.0f/(1.0f+expf(-t1)));
                *(__half2*)&g_g[(size_t)(row+8)*D_DIM + jg] =
                    __floats2half2_rn(1.0f/(1.0f+expf(-t2)), 1.0f/(1.0f+expf(-t3)));
            }
        }
    }
}

// ============================================================
// Kernel 5: attention GEMM, SINGLE fp16 operands, 64x64 warp
//   tiles (BM=128, BN=256); stage = A 16KB + B 32KB, x2 stages
// ============================================================
__global__ __launch_bounds__(256, 1) void k_gemm_att_mma()
{
    extern __shared__ __align__(128) char smem[];
    const uint32_t STAGE = 49152;
    int tid = threadIdx.x;
    int qt = blockIdx.x, nt = blockIdx.y, h = blockIdx.z;
    int wid = tid >> 5, lane = tid & 31;
    int warpM = wid >> 2, warpN = wid & 3;
    uint32_t sbase = smem_u32(smem);

    const char* aH  = (const char*)(g_wh + (size_t)(h*3   + qt) * NKC * 8192);
    const char* bH0 = (const char*)(g_vh + (size_t)(h*128 + nt*2    ) * NKC * 8192);
    const char* bH1 = (const char*)(g_vh + (size_t)(h*128 + nt*2 + 1) * NKC * 8192);

    float acc[4][8][4] = {};

    auto load_chunk = [&](int kc, int stage){
        size_t cb = (size_t)kc * 16384;
        #pragma unroll
        for (int t = 0; t < 12; t++) {
            int tile = t >> 2;                   // 3 tiles of 16KB
            int c    = (t & 3) * 256 + tid;
            uint32_t x = (uint32_t)c * 16;
            uint32_t dst = sbase + stage*STAGE + (uint32_t)tile*16384
                         + (x ^ ((x >> 3) & 0x70));
            const char* src = (tile == 0 ? aH : tile == 1 ? bH0 : bH1) + cb + x;
            cpasync16(dst, src);
        }
        asm volatile("cp.async.commit_group;" ::: "memory");
    };

    load_chunk(0, 0);
    for (int kc = 0; kc < NKC; kc++) {
        int stage = kc & 1;
        if (kc < NKC-1) load_chunk(kc+1, stage ^ 1);
        if (kc < NKC-1) asm volatile("cp.async.wait_group 1;" ::: "memory");
        else            asm volatile("cp.async.wait_group 0;" ::: "memory");
        __syncthreads();

        uint32_t sA = sbase + stage*STAGE;
        uint32_t sB = sA + 16384;            // 32KB: rows 0..255

        #pragma unroll
        for (int kt = 0; kt < 4; kt++) {
            uint32_t a[4][4], b[8][2];
            #pragma unroll
            for (int mt = 0; mt < 4; mt++) {
                int row = warpM*64 + mt*16 + (lane & 15);
                uint32_t x = (uint32_t)row*128 + kt*32 + ((lane >> 4)*16);
                uint32_t sw = x ^ ((x >> 3) & 0x70);
                LDSM_X4(a[mt][0], a[mt][1], a[mt][2], a[mt][3], sA + sw);
            }
            #pragma unroll
            for (int bh = 0; bh < 2; bh++) {
                #pragma unroll
                for (int p = 0; p < 2; p++) {
                    int g = lane >> 3;
                    int ntl = p*2 + (g >> 1);
                    int row = warpN*64 + bh*32 + ntl*8 + (lane & 7);
                    uint32_t x = (uint32_t)row*128 + kt*32 + (g & 1)*16;
                    uint32_t sw = x ^ ((x >> 3) & 0x70);
                    uint32_t r[4];
                    LDSM_X4(r[0], r[1], r[2], r[3], sB + sw);
                    b[bh*4 + p*2    ][0] = r[0]; b[bh*4 + p*2    ][1] = r[1];
                    b[bh*4 + p*2 + 1][0] = r[2]; b[bh*4 + p*2 + 1][1] = r[3];
                }
            }
            #pragma unroll
            for (int mt = 0; mt < 4; mt++)
                #pragma unroll
                for (int nn = 0; nn < 8; nn++)
                    mma_fp16(acc[mt][nn], a[mt], b[nn]);
        }
        __syncthreads();
    }

    // ---- epilogue: fp16 stores into g_o[(s*384+q)*256 + h*32 + c] ----
    #pragma unroll
    for (int mt = 0; mt < 4; mt++) {
        int q = qt*128 + warpM*64 + mt*16 + (lane >> 2);
        #pragma unroll
        for (int nn = 0; nn < 8; nn++) {
            int n = nt*256 + warpN*64 + (nn >> 2)*32 + (nn & 3)*8 + (lane & 3)*2;
            int s = n >> 5, c = n & 31;
            size_t b0 = ((size_t)s*N_DIM + q    )*D_DIM + h*C_DIM + c;
            size_t b1 = ((size_t)s*N_DIM + q + 8)*D_DIM + h*C_DIM + c;
            *(__half2*)&g_o[b0] = __floats2half2_rn(acc[mt][nn][0], acc[mt][nn][1]);
            *(__half2*)&g_o[b1] = __floats2half2_rn(acc[mt][nn][2], acc[mt][nn][3]);
        }
    }
}

// ============================================================
// Kernel 6: output projection via mma.sync SINGLE fp16
//   per CTA: M=128, N=64, K=256. A = hmul(o,g) fp16;
//   B = w_o^T fp16, loaded ONCE (4 chunk-tiles of 8KB).
// ============================================================
__global__ __launch_bounds__(256, 2) void k_gemm_out_mma(const float* __restrict__ b_o,
                                                         float* __restrict__ out)
{
    __shared__ __align__(128) char smem[49152];
    uint32_t sbase = smem_u32(smem);
    uint32_t sA = sbase, sB = sbase + 16384;     // B: 4 chunks x 8KB
    int tid = threadIdx.x;
    int m0  = blockIdx.x * 128;
    int wid = tid >> 5, lane = tid & 31;
    int warpM = wid >> 1, warpN = wid & 1;

    // ---- load ALL of B once: 32KB, 4 chunk-tiles (64 rows x 128B) ----
    #pragma unroll
    for (int u = 0; u < 8; u++) {
        int idx = u*256 + tid;                   // 0..2047 16B-chunks
        int kcb = idx >> 9, rem = idx & 511;     // chunk tile, 512 per tile
        int n = rem >> 3, j = rem & 7;
        uint32_t x = (uint32_t)n*128 + j*16;
        uint32_t dst = sB + (uint32_t)kcb*8192 + (x ^ ((x >> 3) & 0x70));
        cpasync16(dst, g_wot16 + n*256 + kcb*64 + j*8);
    }
    asm volatile("cp.async.commit_group;" ::: "memory");

    float acc[2][4][4] = {};
    int arow = tid >> 1, ahalf = tid & 1;

    for (int k0 = 0; k0 < D_DIM; k0 += 64) {
        // ---- A: o*g via hmul2 (single fp16 rounding) -> smem ----
        {
            size_t base = (size_t)(m0 + arow)*D_DIM + k0 + ahalf*32;
            uint32_t xb = (uint32_t)arow*128 + ahalf*64;
            #pragma unroll
            for (int u = 0; u < 4; u++) {
                uint4 ov = *(const uint4*)(g_o + base + u*8);
                uint4 gv = *(const uint4*)(g_g + base + u*8);
                const __half2* po = (const __half2*)&ov;
                const __half2* pg = (const __half2*)&gv;
                uint4 hv;
                uint32_t* ph = (uint32_t*)&hv;
                #pragma unroll
                for (int j = 0; j < 4; j++) {
                    __half2 pr = __hmul2(po[j], pg[j]);
                    ph[j] = *(uint32_t*)&pr;
                }
                uint32_t x = xb + u*16;
                uint32_t sw = x ^ ((x >> 3) & 0x70);
                *(uint4*)(smem + sw) = hv;
            }
        }
        if (k0 == 0) asm volatile("cp.async.wait_group 0;" ::: "memory");
        __syncthreads();

        uint32_t sBc = sB + (uint32_t)(k0 >> 6)*8192;
        #pragma unroll
        for (int kt = 0; kt < 4; kt++) {
            uint32_t a[2][4], b[4][2];
            #pragma unroll
            for (int mt = 0; mt < 2; mt++) {
                int row = warpM*32 + mt*16 + (lane & 15);
                uint32_t x = (uint32_t)row*128 + kt*32 + ((lane >> 4)*16);
                uint32_t sw = x ^ ((x >> 3) & 0x70);
                LDSM_X4(a[mt][0], a[mt][1], a[mt][2], a[mt][3], sA + sw);
            }
            #pragma unroll
            for (int p = 0; p < 2; p++) {
                int g = lane >> 3;
                int ntile = p*2 + (g >> 1);
                int row = warpN*32 + ntile*8 + (lane & 7);
                uint32_t x = (uint32_t)row*128 + kt*32 + (g & 1)*16;
                uint32_t sw = x ^ ((x >> 3) & 0x70);
                uint32_t r[4];
                LDSM_X4(r[0], r[1], r[2], r[3], sBc + sw);
                b[p*2][0] = r[0]; b[p*2][1] = r[1];
                b[p*2+1][0] = r[2]; b[p*2+1][1] = r[3];
            }
            #pragma unroll
            for (int mt = 0; mt < 2; mt++)
                #pragma unroll
                for (int nn = 0; nn < 4; nn++)
                    mma_fp16(acc[mt][nn], a[mt], b[nn]);
        }
        __syncthreads();
    }

    #pragma unroll
    for (int mt = 0; mt < 2; mt++) {
        int row = m0 + warpM*32 + mt*16 + (lane >> 2);
        #pragma unroll
        for (int nn = 0; nn < 4; nn++) {
            int col = warpN*32 + nn*8 + (lane & 3)*2;
            float b0 = b_o[col], b1 = b_o[col+1];
            *(float2*)(out + (size_t)row*CIN + col) =
                make_float2(acc[mt][nn][0] + b0, acc[mt][nn][1] + b1);
            *(float2*)(out + (size_t)(row+8)*CIN + col) =
                make_float2(acc[mt][nn][2] + b0, acc[mt][nn][3] + b1);
        }
    }
}

// ============================================================
extern "C" void kernel_launch(void* const* d_in, const int* in_sizes, int n_in,
                              void* d_out, int out_size)
{
    const float* m       = (const float*)d_in[0];
    const float* z       = (const float*)d_in[1];
    const float* mask    = (const float*)d_in[2];
    const float* gamma_m = (const float*)d_in[3];
    const float* beta_m  = (const float*)d_in[4];
    const float* gamma_z = (const float*)d_in[5];
    const float* beta_z  = (const float*)d_in[6];
    const float* w_z     = (const float*)d_in[7];
    const float* b_z     = (const float*)d_in[8];
    const float* w_v     = (const float*)d_in[9];
    const float* b_v     = (const float*)d_in[10];
    const float* w_g     = (const float*)d_in[11];
    const float* b_g     = (const float*)d_in[12];
    const float* w_o     = (const float*)d_in[13];
    const float* b_o     = (const float*)d_in[14];
    float* out = (float*)d_out;

    cudaFuncSetAttribute(k_gemm_att_mma, cudaFuncAttributeMaxDynamicSharedMemorySize, 98304);
    cudaFuncSetAttribute(k_gemm_vg_mma,  cudaFuncAttributeMaxDynamicSharedMemorySize, 34816);

    k_prep_w<<<512, 64>>>(w_v, w_g);
    k_prep_wo<<<64, 256>>>(w_o);
    k_lnz_logits<<<(N_DIM*N_DIM)/8, 256>>>(z, mask, gamma_z, beta_z, w_z, b_z);
    k_softmax<<<H_DIM*N_DIM, 128>>>();
    k_lnm<<<MROWS/8, 256>>>(m, gamma_m, beta_m);
    k_gemm_vg_mma<<<dim3(4, MROWS/128), 256, 34816>>>(b_v, b_g);
    k_gemm_att_mma<<<dim3(3, 64, 8), 256, 98304>>>();
    k_gemm_out_mma<<<MROWS/128, 256>>>(b_o, out);
}

// round 17
// speedup vs baseline: 1.6982x; 1.0538x over previous
#include <cuda_runtime.h>
#include <cuda_bf16.h>
#include <cuda_fp16.h>
#include <math.h>
#include <stdint.h>

#define S_DIM 512
#define N_DIM 384
#define CIN   64
#define CZ    128
#define H_DIM 8
#define C_DIM 32
#define D_DIM 256
#define INF_  1e9f
#define EPS_  1e-5f
#define MROWS (S_DIM*N_DIM)   // 196608
#define NKC   6               // K chunks of 64 covering K=384

// ---- scratch (static device arrays: no allocations allowed) ----
__device__ float g_w [(size_t)H_DIM*N_DIM*N_DIM];   // logits [h][q][k]
__device__ __half g_g [(size_t)MROWS*D_DIM];        // gate (fp16)
__device__ __half g_o [(size_t)MROWS*D_DIM];        // attention output (fp16)
// LN(m) single-fp16, k-major rows of 64 (128B rows)
__device__ __align__(1024) __half g_mn16[(size_t)MROWS*CIN];
// transposed [n=512][k=64] single-fp16 weights (w_v | w_g)
__device__ __align__(1024) __half g_wt16[512*64];
// transposed [n=64][k=256] single-fp16 w_o
__device__ __align__(1024) __half g_wot16[64*256];
// SINGLE-fp16 k-major staging tiles, 128 rows x 64 k each (8192 elems, 16KB)
// w: [h][qt(3)][kc(6)]   v: [h][nt(128)][kc(6)]
__device__ __align__(1024) __half g_wh[(size_t)H_DIM*3*NKC*8192];
__device__ __align__(1024) __half g_vh[(size_t)H_DIM*128*NKC*8192];

// ============================================================
// helpers (Ampere-class ISA only: valid on base sm_103 target)
// ============================================================
__device__ __forceinline__ uint32_t smem_u32(const void* p){
    uint32_t a;
    asm("{ .reg .u64 t; cvta.to.shared.u64 t, %1; cvt.u32.u64 %0, t; }" : "=r"(a) : "l"(p));
    return a;
}
#define LDSM_X4(r0,r1,r2,r3,addr) \
    asm volatile("ldmatrix.sync.aligned.m8n8.x4.shared.b16 {%0,%1,%2,%3}, [%4];" \
        : "=r"(r0),"=r"(r1),"=r"(r2),"=r"(r3) : "r"(addr))
__device__ __forceinline__ void mma_fp16(float* c, const uint32_t* a, const uint32_t* b){
    asm volatile("mma.sync.aligned.m16n8k16.row.col.f32.f16.f16.f32 "
        "{%0,%1,%2,%3}, {%4,%5,%6,%7}, {%8,%9}, {%0,%1,%2,%3};"
        : "+f"(c[0]),"+f"(c[1]),"+f"(c[2]),"+f"(c[3])
        : "r"(a[0]),"r"(a[1]),"r"(a[2]),"r"(a[3]), "r"(b[0]),"r"(b[1]));
}
__device__ __forceinline__ void cpasync16(uint32_t dst, const void* src){
    asm volatile("cp.async.cg.shared.global [%0], [%1], 16;" :: "r"(dst), "l"(src));
}

// ============================================================
// Kernel 0a: transpose weights -> g_wt16 [n=512][k=64] (fp16)
// ============================================================
__global__ void k_prep_w(const float* __restrict__ w_v, const float* __restrict__ w_g)
{
    int n = blockIdx.x, k = threadIdx.x;   // 512 blocks x 64 threads
    float val = (n < D_DIM) ? w_v[k*D_DIM + n] : w_g[k*D_DIM + (n - D_DIM)];
    g_wt16[n*64 + k] = __float2half_rn(val);
}

// ============================================================
// Kernel 0b: transpose w_o -> g_wot16 [n=64][k=256] (fp16)
// ============================================================
__global__ void k_prep_wo(const float* __restrict__ w_o)
{
    int n = blockIdx.x, k = threadIdx.x;   // 64 blocks x 256 threads
    g_wot16[n*256 + k] = __float2half_rn(w_o[k*CIN + n]);
}

// ============================================================
// Kernel 1: LN(z) + logits (warp per (q,k) row)
// ============================================================
__global__ void k_lnz_logits(const float* __restrict__ z, const float* __restrict__ mask,
                             const float* __restrict__ gamma_z, const float* __restrict__ beta_z,
                             const float* __restrict__ w_z, const float* __restrict__ b_z)
{
    int gw   = (blockIdx.x * blockDim.x + threadIdx.x) >> 5;
    int lane = threadIdx.x & 31;
    if (gw >= N_DIM * N_DIM) return;
    int q = gw / N_DIM, k = gw % N_DIM;
    const float* zp = z + (size_t)gw * CZ;

    float x0 = zp[lane], x1 = zp[lane+32], x2 = zp[lane+64], x3 = zp[lane+96];
    float s  = x0+x1+x2+x3;
    float s2 = x0*x0 + x1*x1 + x2*x2 + x3*x3;
    #pragma unroll
    for (int o = 16; o; o >>= 1) {
        s  += __shfl_xor_sync(0xffffffffu, s,  o);
        s2 += __shfl_xor_sync(0xffffffffu, s2, o);
    }
    float mu  = s * (1.0f / CZ);
    float inv = rsqrtf(s2 * (1.0f / CZ) - mu*mu + EPS_);
    float n0 = (x0-mu)*inv*gamma_z[lane]    + beta_z[lane];
    float n1 = (x1-mu)*inv*gamma_z[lane+32] + beta_z[lane+32];
    float n2 = (x2-mu)*inv*gamma_z[lane+64] + beta_z[lane+64];
    float n3 = (x3-mu)*inv*gamma_z[lane+96] + beta_z[lane+96];

    float acc[H_DIM];
    #pragma unroll
    for (int h = 0; h < H_DIM; h++) {
        acc[h] = n0 * w_z[lane*H_DIM + h]
               + n1 * w_z[(lane+32)*H_DIM + h]
               + n2 * w_z[(lane+64)*H_DIM + h]
               + n3 * w_z[(lane+96)*H_DIM + h];
        #pragma unroll
        for (int o = 16; o; o >>= 1)
            acc[h] += __shfl_xor_sync(0xffffffffu, acc[h], o);
    }
    if (lane == 0) {
        float bias = INF_ * (mask[gw] - 1.0f);
        #pragma unroll
        for (int h = 0; h < H_DIM; h++)
            g_w[((size_t)h*N_DIM + q)*N_DIM + k] = acc[h] + b_z[h] + bias;
    }
}

// ============================================================
// Kernel 2: softmax per (h,q) row -> single-fp16 staging (k-major)
// ============================================================
__global__ void k_softmax()
{
    int row = blockIdx.x;                   // h*384 + q
    int h = row / N_DIM, q = row - h*N_DIM;
    const float* p = g_w + (size_t)row * N_DIM;
    int tid = threadIdx.x;                  // 128 threads, 3 elems each
    __shared__ float red[128];

    float v0 = p[tid], v1 = p[tid+128], v2 = p[tid+256];
    float mx = fmaxf(v0, fmaxf(v1, v2));
    red[tid] = mx; __syncthreads();
    for (int o = 64; o; o >>= 1) { if (tid < o) red[tid] = fmaxf(red[tid], red[tid+o]); __syncthreads(); }
    mx = red[0]; __syncthreads();

    float e0 = expf(v0-mx), e1 = expf(v1-mx), e2 = expf(v2-mx);
    red[tid] = e0 + e1 + e2; __syncthreads();
    for (int o = 64; o; o >>= 1) { if (tid < o) red[tid] += red[tid+o]; __syncthreads(); }
    float inv = 1.0f / red[0];

    int r = q & 127;
    size_t blkbase = (size_t)((h*3 + (q >> 7)) * NKC);
    float ev[3] = {e0, e1, e2};
    #pragma unroll
    for (int t = 0; t < 3; t++) {
        int k = tid + t*128;
        float wv = ev[t] * inv;
        int kc = k >> 6, kk = k & 63;
        size_t off = (blkbase + kc) * 8192 + (size_t)(r*64 + kk);
        g_wh[off] = __float2half_rn(wv);
    }
}

// ============================================================
// Kernel 3: LN(m) -> single-fp16 mn (k-major rows of 64)
// ============================================================
__global__ void k_lnm(const float* __restrict__ m,
                      const float* __restrict__ gamma_m, const float* __restrict__ beta_m)
{
    int gw   = (blockIdx.x * blockDim.x + threadIdx.x) >> 5;
    int lane = threadIdx.x & 31;
    if (gw >= MROWS) return;
    const float* mp = m + (size_t)gw * CIN;
    float a = mp[lane], b = mp[lane+32];
    float s = a + b, s2 = a*a + b*b;
    #pragma unroll
    for (int o = 16; o; o >>= 1) {
        s  += __shfl_xor_sync(0xffffffffu, s,  o);
        s2 += __shfl_xor_sync(0xffffffffu, s2, o);
    }
    float mu  = s * (1.0f / CIN);
    float inv = rsqrtf(s2 * (1.0f / CIN) - mu*mu + EPS_);
    float na = (a-mu)*inv*gamma_m[lane]    + beta_m[lane];
    float nb = (b-mu)*inv*gamma_m[lane+32] + beta_m[lane+32];
    size_t base = (size_t)gw * CIN;
    g_mn16[base + lane]      = __float2half_rn(na);
    g_mn16[base + lane + 32] = __float2half_rn(nb);
}

// ============================================================
// Kernel 4: v/gate projection via mma.sync SINGLE fp16
//   grid (4, 1536); A 16KB + B 16KB operands, fp16 T (35KB)
// ============================================================
__global__ __launch_bounds__(256) void k_gemm_vg_mma(const float* __restrict__ b_v,
                                                     const float* __restrict__ b_g)
{
    extern __shared__ __align__(128) char smem[];
    int tid = threadIdx.x;
    int n0 = blockIdx.x * 128;
    int m0 = blockIdx.y * 128;
    int wid = tid >> 5, lane = tid & 31;
    int warpM = wid >> 2, warpN = wid & 3;
    uint32_t sbase = smem_u32(smem);
    uint32_t sA = sbase, sB = sbase + 16384;

    const char* aSrc = (const char*)(g_mn16 + (size_t)m0*64);
    const char* bSrc = (const char*)(g_wt16 + (size_t)n0*64);

    #pragma unroll
    for (int u = 0; u < 8; u++) {
        int idx = u*256 + tid;              // 0..2047
        int tile = idx >> 10;
        uint32_t x = (uint32_t)(idx & 1023) * 16;
        uint32_t dst = (tile ? sB : sA) + (x ^ ((x >> 3) & 0x70));
        cpasync16(dst, (tile ? bSrc : aSrc) + x);
    }
    asm volatile("cp.async.commit_group;" ::: "memory");
    asm volatile("cp.async.wait_group 0;" ::: "memory");
    __syncthreads();

    float acc[4][4][4] = {};
    #pragma unroll
    for (int kt = 0; kt < 4; kt++) {
        uint32_t a[4][4], b[4][2];
        #pragma unroll
        for (int mt = 0; mt < 4; mt++) {
            int row = warpM*64 + mt*16 + (lane & 15);
            uint32_t x = (uint32_t)row*128 + kt*32 + ((lane >> 4)*16);
            uint32_t sw = x ^ ((x >> 3) & 0x70);
            LDSM_X4(a[mt][0], a[mt][1], a[mt][2], a[mt][3], sA + sw);
        }
        #pragma unroll
        for (int p = 0; p < 2; p++) {
            int g = lane >> 3;
            int ntile = p*2 + (g >> 1);
            int row = warpN*32 + ntile*8 + (lane & 7);
            uint32_t x = (uint32_t)row*128 + kt*32 + (g & 1)*16;
            uint32_t sw = x ^ ((x >> 3) & 0x70);
            uint32_t r[4];
            LDSM_X4(r[0], r[1], r[2], r[3], sB + sw);
            b[p*2][0] = r[0]; b[p*2][1] = r[1];
            b[p*2+1][0] = r[2]; b[p*2+1][1] = r[3];
        }
        #pragma unroll
        for (int mt = 0; mt < 4; mt++)
            #pragma unroll
            for (int nn = 0; nn < 4; nn++)
                mma_fp16(acc[mt][nn], a[mt], b[nn]);
    }
    __syncthreads();

    if (n0 < D_DIM) {
        // ---- v: fp16 transpose buffer T[(col*2+kcl)*68 + kk] ----
        __half* T = (__half*)smem;    // 256*68 halves = 34816 B
        #pragma unroll
        for (int mt = 0; mt < 4; mt++) {
            int qr = warpM*64 + mt*16 + (lane >> 2);
            int qr2 = qr + 8;
            #pragma unroll
            for (int nn = 0; nn < 4; nn++) {
                int nc = warpN*32 + nn*8 + (lane & 3)*2;
                float bv0 = b_v[n0 + nc], bv1 = b_v[n0 + nc + 1];
                T[((nc  )*2 + (qr  >> 6))*68 + (qr  & 63)] = __float2half_rn(acc[mt][nn][0] + bv0);
                T[((nc+1)*2 + (qr  >> 6))*68 + (qr  & 63)] = __float2half_rn(acc[mt][nn][1] + bv1);
                T[((nc  )*2 + (qr2 >> 6))*68 + (qr2 & 63)] = __float2half_rn(acc[mt][nn][2] + bv0);
                T[((nc+1)*2 + (qr2 >> 6))*68 + (qr2 & 63)] = __float2half_rn(acc[mt][nn][3] + bv1);
            }
        }
        __syncthreads();

        int sI = m0 / N_DIM;
        int kb = m0 - sI * N_DIM;
        int nt = sI >> 2;
        int j   = tid >> 1, kcl = tid & 1;
        int col = n0 + j;
        int h   = col >> 5, c = col & 31;
        int nr  = ((sI & 3) << 5) + c;
        int kc  = (kb >> 6) + kcl;
        size_t blk = ((size_t)(h*128 + nt)*NKC + kc) * 8192;
        const __half* Tr = T + (j*2 + kcl)*68;
        #pragma unroll
        for (int kk = 0; kk < 64; kk += 2) {
            *(__half2*)&g_vh[blk + (size_t)nr*64 + kk] = *(const __half2*)&Tr[kk];
        }
    } else {
        int jb = n0 - D_DIM;
        #pragma unroll
        for (int mt = 0; mt < 4; mt++) {
            int row = m0 + warpM*64 + mt*16 + (lane >> 2);
            #pragma unroll
            for (int nn = 0; nn < 4; nn++) {
                int jg = jb + warpN*32 + nn*8 + (lane & 3)*2;
                float bg0 = b_g[jg], bg1 = b_g[jg+1];
                float t0 = acc[mt][nn][0] + bg0, t1 = acc[mt][nn][1] + bg1;
                float t2 = acc[mt][nn][2] + bg0, t3 = acc[mt][nn][3] + bg1;
                *(__half2*)&g_g[(size_t)row*D_DIM + jg] =
                    __floats2half2_rn(1.0f/(1.0f+expf(-t0)), 1.0f/(1.0f+expf(-t1)));
                *(__half2*)&g_g[(size_t)(row+8)*D_DIM + jg] =
                    __floats2half2_rn(1.0f/(1.0f+expf(-t2)), 1.0f/(1.0f+expf(-t3)));
            }
        }
    }
}

// ============================================================
// Kernel 5: attention GEMM, SINGLE fp16, BM=128 BN=128,
//   64x32 warp tiles -> 64 acc regs -> 2 CTAs/SM.
//   stage = A 16KB + B 16KB = 32KB, x2 stages
// ============================================================
__global__ __launch_bounds__(256, 2) void k_gemm_att_mma()
{
    extern __shared__ __align__(128) char smem[];
    const uint32_t STAGE = 32768;
    int tid = threadIdx.x;
    int qt = blockIdx.x, nt = blockIdx.y, h = blockIdx.z;
    int wid = tid >> 5, lane = tid & 31;
    int warpM = wid >> 2, warpN = wid & 3;
    uint32_t sbase = smem_u32(smem);

    const char* aH = (const char*)(g_wh + (size_t)(h*3   + qt) * NKC * 8192);
    const char* bH = (const char*)(g_vh + (size_t)(h*128 + nt) * NKC * 8192);

    float acc[4][4][4] = {};

    auto load_chunk = [&](int kc, int stage){
        size_t cb = (size_t)kc * 16384;
        #pragma unroll
        for (int t = 0; t < 8; t++) {
            int tile = t >> 2;                   // 2 tiles of 16KB
            int c    = (t & 3) * 256 + tid;
            uint32_t x = (uint32_t)c * 16;
            uint32_t dst = sbase + stage*STAGE + (uint32_t)tile*16384
                         + (x ^ ((x >> 3) & 0x70));
            const char* src = (tile == 0 ? aH : bH) + cb + x;
            cpasync16(dst, src);
        }
        asm volatile("cp.async.commit_group;" ::: "memory");
    };

    load_chunk(0, 0);
    for (int kc = 0; kc < NKC; kc++) {
        int stage = kc & 1;
        if (kc < NKC-1) load_chunk(kc+1, stage ^ 1);
        if (kc < NKC-1) asm volatile("cp.async.wait_group 1;" ::: "memory");
        else            asm volatile("cp.async.wait_group 0;" ::: "memory");
        __syncthreads();

        uint32_t sA = sbase + stage*STAGE;
        uint32_t sB = sA + 16384;

        #pragma unroll
        for (int kt = 0; kt < 4; kt++) {
            uint32_t a[4][4], b[4][2];
            #pragma unroll
            for (int mt = 0; mt < 4; mt++) {
                int row = warpM*64 + mt*16 + (lane & 15);
                uint32_t x = (uint32_t)row*128 + kt*32 + ((lane >> 4)*16);
                uint32_t sw = x ^ ((x >> 3) & 0x70);
                LDSM_X4(a[mt][0], a[mt][1], a[mt][2], a[mt][3], sA + sw);
            }
            #pragma unroll
            for (int p = 0; p < 2; p++) {
                int g = lane >> 3;
                int ntile = p*2 + (g >> 1);
                int row = warpN*32 + ntile*8 + (lane & 7);
                uint32_t x = (uint32_t)row*128 + kt*32 + (g & 1)*16;
                uint32_t sw = x ^ ((x >> 3) & 0x70);
                uint32_t r[4];
                LDSM_X4(r[0], r[1], r[2], r[3], sB + sw);
                b[p*2][0] = r[0]; b[p*2][1] = r[1];
                b[p*2+1][0] = r[2]; b[p*2+1][1] = r[3];
            }
            #pragma unroll
            for (int mt = 0; mt < 4; mt++)
                #pragma unroll
                for (int nn = 0; nn < 4; nn++)
                    mma_fp16(acc[mt][nn], a[mt], b[nn]);
        }
        __syncthreads();
    }

    // ---- epilogue: fp16 stores into g_o[(s*384+q)*256 + h*32 + c] ----
    #pragma unroll
    for (int mt = 0; mt < 4; mt++) {
        int q = qt*128 + warpM*64 + mt*16 + (lane >> 2);
        #pragma unroll
        for (int nn = 0; nn < 4; nn++) {
            int n = nt*128 + warpN*32 + nn*8 + (lane & 3)*2;
            int s = n >> 5, c = n & 31;
            size_t b0 = ((size_t)s*N_DIM + q    )*D_DIM + h*C_DIM + c;
            size_t b1 = ((size_t)s*N_DIM + q + 8)*D_DIM + h*C_DIM + c;
            *(__half2*)&g_o[b0] = __floats2half2_rn(acc[mt][nn][0], acc[mt][nn][1]);
            *(__half2*)&g_o[b1] = __floats2half2_rn(acc[mt][nn][2], acc[mt][nn][3]);
        }
    }
}

// ============================================================
// Kernel 6: output projection via mma.sync SINGLE fp16
//   per CTA: M=128, N=64, K=256. A = hmul(o,g) fp16;
//   B = w_o^T fp16, loaded ONCE (4 chunk-tiles of 8KB).
// ============================================================
__global__ __launch_bounds__(256, 2) void k_gemm_out_mma(const float* __restrict__ b_o,
                                                         float* __restrict__ out)
{
    __shared__ __align__(128) char smem[49152];
    uint32_t sbase = smem_u32(smem);
    uint32_t sA = sbase, sB = sbase + 16384;     // B: 4 chunks x 8KB
    int tid = threadIdx.x;
    int m0  = blockIdx.x * 128;
    int wid = tid >> 5, lane = tid & 31;
    int warpM = wid >> 1, warpN = wid & 1;

    // ---- load ALL of B once: 32KB, 4 chunk-tiles (64 rows x 128B) ----
    #pragma unroll
    for (int u = 0; u < 8; u++) {
        int idx = u*256 + tid;                   // 0..2047 16B-chunks
        int kcb = idx >> 9, rem = idx & 511;     // chunk tile, 512 per tile
        int n = rem >> 3, j = rem & 7;
        uint32_t x = (uint32_t)n*128 + j*16;
        uint32_t dst = sB + (uint32_t)kcb*8192 + (x ^ ((x >> 3) & 0x70));
        cpasync16(dst, g_wot16 + n*256 + kcb*64 + j*8);
    }
    asm volatile("cp.async.commit_group;" ::: "memory");

    float acc[2][4][4] = {};
    int arow = tid >> 1, ahalf = tid & 1;

    for (int k0 = 0; k0 < D_DIM; k0 += 64) {
        // ---- A: o*g via hmul2 (single fp16 rounding) -> smem ----
        {
            size_t base = (size_t)(m0 + arow)*D_DIM + k0 + ahalf*32;
            uint32_t xb = (uint32_t)arow*128 + ahalf*64;
            #pragma unroll
            for (int u = 0; u < 4; u++) {
                uint4 ov = *(const uint4*)(g_o + base + u*8);
                uint4 gv = *(const uint4*)(g_g + base + u*8);
                const __half2* po = (const __half2*)&ov;
                const __half2* pg = (const __half2*)&gv;
                uint4 hv;
                uint32_t* ph = (uint32_t*)&hv;
                #pragma unroll
                for (int j = 0; j < 4; j++) {
                    __half2 pr = __hmul2(po[j], pg[j]);
                    ph[j] = *(uint32_t*)&pr;
                }
                uint32_t x = xb + u*16;
                uint32_t sw = x ^ ((x >> 3) & 0x70);
                *(uint4*)(smem + sw) = hv;
            }
        }
        if (k0 == 0) asm volatile("cp.async.wait_group 0;" ::: "memory");
        __syncthreads();

        uint32_t sBc = sB + (uint32_t)(k0 >> 6)*8192;
        #pragma unroll
        for (int kt = 0; kt < 4; kt++) {
            uint32_t a[2][4], b[4][2];
            #pragma unroll
            for (int mt = 0; mt < 2; mt++) {
                int row = warpM*32 + mt*16 + (lane & 15);
                uint32_t x = (uint32_t)row*128 + kt*32 + ((lane >> 4)*16);
                uint32_t sw = x ^ ((x >> 3) & 0x70);
                LDSM_X4(a[mt][0], a[mt][1], a[mt][2], a[mt][3], sA + sw);
            }
            #pragma unroll
            for (int p = 0; p < 2; p++) {
                int g = lane >> 3;
                int ntile = p*2 + (g >> 1);
                int row = warpN*32 + ntile*8 + (lane & 7);
                uint32_t x = (uint32_t)row*128 + kt*32 + (g & 1)*16;
                uint32_t sw = x ^ ((x >> 3) & 0x70);
                uint32_t r[4];
                LDSM_X4(r[0], r[1], r[2], r[3], sBc + sw);
                b[p*2][0] = r[0]; b[p*2][1] = r[1];
                b[p*2+1][0] = r[2]; b[p*2+1][1] = r[3];
            }
            #pragma unroll
            for (int mt = 0; mt < 2; mt++)
                #pragma unroll
                for (int nn = 0; nn < 4; nn++)
                    mma_fp16(acc[mt][nn], a[mt], b[nn]);
        }
        __syncthreads();
    }

    #pragma unroll
    for (int mt = 0; mt < 2; mt++) {
        int row = m0 + warpM*32 + mt*16 + (lane >> 2);
        #pragma unroll
        for (int nn = 0; nn < 4; nn++) {
            int col = warpN*32 + nn*8 + (lane & 3)*2;
            float b0 = b_o[col], b1 = b_o[col+1];
            *(float2*)(out + (size_t)row*CIN + col) =
                make_float2(acc[mt][nn][0] + b0, acc[mt][nn][1] + b1);
            *(float2*)(out + (size_t)(row+8)*CIN + col) =
                make_float2(acc[mt][nn][2] + b0, acc[mt][nn][3] + b1);
        }
    }
}

// ============================================================
extern "C" void kernel_launch(void* const* d_in, const int* in_sizes, int n_in,
                              void* d_out, int out_size)
{
    const float* m       = (const float*)d_in[0];
    const float* z       = (const float*)d_in[1];
    const float* mask    = (const float*)d_in[2];
    const float* gamma_m = (const float*)d_in[3];
    const float* beta_m  = (const float*)d_in[4];
    const float* gamma_z = (const float*)d_in[5];
    const float* beta_z  = (const float*)d_in[6];
    const float* w_z     = (const float*)d_in[7];
    const float* b_z     = (const float*)d_in[8];
    const float* w_v     = (const float*)d_in[9];
    const float* b_v     = (const float*)d_in[10];
    const float* w_g     = (const float*)d_in[11];
    const float* b_g     = (const float*)d_in[12];
    const float* w_o     = (const float*)d_in[13];
    const float* b_o     = (const float*)d_in[14];
    float* out = (float*)d_out;

    cudaFuncSetAttribute(k_gemm_att_mma, cudaFuncAttributeMaxDynamicSharedMemorySize, 65536);
    cudaFuncSetAttribute(k_gemm_vg_mma,  cudaFuncAttributeMaxDynamicSharedMemorySize, 34816);

    k_prep_w<<<512, 64>>>(w_v, w_g);
    k_prep_wo<<<64, 256>>>(w_o);
    k_lnz_logits<<<(N_DIM*N_DIM)/8, 256>>>(z, mask, gamma_z, beta_z, w_z, b_z);
    k_softmax<<<H_DIM*N_DIM, 128>>>();
    k_lnm<<<MROWS/8, 256>>>(m, gamma_m, beta_m);
    k_gemm_vg_mma<<<dim3(4, MROWS/128), 256, 34816>>>(b_v, b_g);
    k_gemm_att_mma<<<dim3(3, 128, 8), 256, 65536>>>();
    k_gemm_out_mma<<<MROWS/128, 256>>>(b_o, out);
}